// round 1
// baseline (speedup 1.0000x reference)
#include <cuda_runtime.h>
#include <cuda_bf16.h>

// Problem constants
#define B_   2
#define N_   4096
#define C_   512
#define H_   8
#define D_   64
#define INNER_ (H_ * D_)          // 512
#define QKVCOLS_ (INNER_ * 3)     // 1536
#define M_ (B_ * N_)              // 8192

// Scratch (device globals; no cudaMalloc allowed)
__device__ float g_q[B_ * H_ * N_ * D_];   // 16 MB
__device__ float g_k[B_ * H_ * N_ * D_];   // 16 MB
__device__ float g_v[B_ * H_ * N_ * D_];   // 16 MB
__device__ float g_oh[B_ * N_ * INNER_];   // 16 MB, [B,N,H*d]

// ---------------------------------------------------------------------------
// K1: QKV GEMM.  x[M,512] @ w[512,1536] -> scatter into g_q/g_k/g_v [B,H,N,d]
// 64x64 tile, BK=16, 256 threads, 4x4 micro-tile
// ---------------------------------------------------------------------------
__global__ __launch_bounds__(256) void gemm_qkv_kernel(
    const float* __restrict__ x, const float* __restrict__ w)
{
    __shared__ float As[16 * 68];  // transposed: As[k][m]
    __shared__ float Bs[16 * 68];  // Bs[k][n]

    const int tid = threadIdx.x;
    const int ty = tid >> 4;       // 0..15
    const int tx = tid & 15;       // 0..15
    const int m0 = blockIdx.y * 64;
    const int n0 = blockIdx.x * 64;

    float acc[4][4] = {};

    for (int k0 = 0; k0 < C_; k0 += 16) {
        // load A tile (64 rows x 16 cols), transposed into As[k][m]
        {
            const int r = tid >> 4, c = tid & 15;
            #pragma unroll
            for (int p = 0; p < 4; p++) {
                int rr = r + p * 16;
                As[c * 68 + rr] = x[(size_t)(m0 + rr) * C_ + k0 + c];
            }
        }
        // load B tile (16 rows x 64 cols)
        {
            const int r2 = tid >> 6, c2 = tid & 63;
            #pragma unroll
            for (int p = 0; p < 4; p++) {
                int rr = r2 + p * 4;
                Bs[rr * 68 + c2] = w[(size_t)(k0 + rr) * QKVCOLS_ + n0 + c2];
            }
        }
        __syncthreads();

        #pragma unroll
        for (int k = 0; k < 16; k++) {
            float4 a = *(const float4*)&As[k * 68 + ty * 4];
            float4 b = *(const float4*)&Bs[k * 68 + tx * 4];
            float av[4] = {a.x, a.y, a.z, a.w};
            float bv[4] = {b.x, b.y, b.z, b.w};
            #pragma unroll
            for (int i = 0; i < 4; i++)
                #pragma unroll
                for (int j = 0; j < 4; j++)
                    acc[i][j] += av[i] * bv[j];
        }
        __syncthreads();
    }

    // epilogue: scatter to q/k/v in [B,H,N,d]
    #pragma unroll
    for (int i = 0; i < 4; i++) {
        const int row = m0 + ty * 4 + i;
        const int b = row >> 12;          // /4096
        const int n = row & (N_ - 1);
        #pragma unroll
        for (int j = 0; j < 4; j++) {
            const int col = n0 + tx * 4 + j;
            const int part = col >> 9;    // /512
            const int rem = col & 511;
            const int h = rem >> 6;
            const int dd = rem & 63;
            size_t idx = ((size_t)(b * H_ + h) * N_ + n) * D_ + dd;
            float* dst = (part == 0) ? g_q : (part == 1) ? g_k : g_v;
            dst[idx] = acc[i][j];
        }
    }
}

// ---------------------------------------------------------------------------
// K2: RoPE in-place on g_q or g_k. Each thread owns pair (j, j+32).
// ---------------------------------------------------------------------------
__global__ __launch_bounds__(256) void rope_kernel(
    const float* __restrict__ pos, int which)
{
    float* buf = (which == 0) ? g_q : g_k;
    const long total = (long)B_ * H_ * N_ * (D_ / 2);
    long i = (long)blockIdx.x * blockDim.x + threadIdx.x;
    if (i >= total) return;
    const int half = (int)(i & 31);
    const long rest = i >> 5;             // (b*H+h)*N + n
    const int n = (int)(rest & (N_ - 1));
    const long base = rest << 6;          // *64

    const float p1 = pos[n * D_ + half];
    const float p2 = pos[n * D_ + half + 32];
    const float t1 = buf[base + half];
    const float t2 = buf[base + half + 32];
    buf[base + half]      = t1 * cosf(p1) - t2 * sinf(p1);
    buf[base + half + 32] = t2 * cosf(p2) + t1 * sinf(p2);
}

// ---------------------------------------------------------------------------
// K3: fused attention (flash style). BR=64 queries/block, BC=32 keys/tile.
// 256 threads = 16x16 grid. QK micro: 4 rows x 2 cols. PV micro: 4x4.
// Writes O directly to [B,N,H*d].
// ---------------------------------------------------------------------------
__global__ __launch_bounds__(256) void flash_kernel()
{
    __shared__ float Qs[64 * 68];
    __shared__ float Ks[32 * 68];
    __shared__ float Vs[32 * 68];
    __shared__ float Ss[64 * 36];

    const int tid = threadIdx.x;
    const int ty = tid >> 4;   // 0..15 -> row group of 4
    const int tx = tid & 15;   // 0..15
    const int bh = blockIdx.y;            // b*H + h
    const int b = bh >> 3;
    const int h = bh & 7;
    const int q0 = blockIdx.x * 64;
    const float scale = 0.125f;           // d^-0.5

    // load Q tile (pre-scaled)
    {
        const size_t qbase = ((size_t)bh * N_ + q0) * D_;
        for (int t = tid; t < 64 * 16; t += 256) {
            int row = t >> 4, qd = t & 15;
            float4 v = *(const float4*)&g_q[qbase + (size_t)row * D_ + qd * 4];
            v.x *= scale; v.y *= scale; v.z *= scale; v.w *= scale;
            *(float4*)&Qs[row * 68 + qd * 4] = v;
        }
    }

    float o[4][4] = {};
    float m[4] = {-1e30f, -1e30f, -1e30f, -1e30f};
    float l[4] = {};

    __syncthreads();

    for (int kt = 0; kt < N_ / 32; kt++) {
        // load K/V tiles
        const size_t kbase = ((size_t)bh * N_ + (size_t)kt * 32) * D_;
        for (int t = tid; t < 32 * 16; t += 256) {
            int row = t >> 4, qd = t & 15;
            *(float4*)&Ks[row * 68 + qd * 4] =
                *(const float4*)&g_k[kbase + (size_t)row * D_ + qd * 4];
            *(float4*)&Vs[row * 68 + qd * 4] =
                *(const float4*)&g_v[kbase + (size_t)row * D_ + qd * 4];
        }
        __syncthreads();

        // S = Q K^T  (rows ty*4+i, cols tx*2+j)
        float s[4][2] = {};
        #pragma unroll
        for (int kk = 0; kk < 64; kk += 4) {
            float4 bb[2];
            #pragma unroll
            for (int j = 0; j < 2; j++)
                bb[j] = *(const float4*)&Ks[(tx * 2 + j) * 68 + kk];
            #pragma unroll
            for (int i = 0; i < 4; i++) {
                float4 a = *(const float4*)&Qs[(ty * 4 + i) * 68 + kk];
                #pragma unroll
                for (int j = 0; j < 2; j++)
                    s[i][j] += a.x * bb[j].x + a.y * bb[j].y +
                               a.z * bb[j].z + a.w * bb[j].w;
            }
        }

        // online softmax (row reductions across the 16 tx lanes)
        #pragma unroll
        for (int i = 0; i < 4; i++) {
            float mt = fmaxf(s[i][0], s[i][1]);
            #pragma unroll
            for (int off = 8; off >= 1; off >>= 1)
                mt = fmaxf(mt, __shfl_xor_sync(0xffffffffu, mt, off, 16));
            const float mn = fmaxf(m[i], mt);
            const float alpha = __expf(m[i] - mn);
            const float p0 = __expf(s[i][0] - mn);
            const float p1 = __expf(s[i][1] - mn);
            float pt = p0 + p1;
            #pragma unroll
            for (int off = 8; off >= 1; off >>= 1)
                pt += __shfl_xor_sync(0xffffffffu, pt, off, 16);
            l[i] = l[i] * alpha + pt;
            m[i] = mn;
            #pragma unroll
            for (int j = 0; j < 4; j++) o[i][j] *= alpha;
            Ss[(ty * 4 + i) * 36 + tx * 2 + 0] = p0;
            Ss[(ty * 4 + i) * 36 + tx * 2 + 1] = p1;
        }
        __syncthreads();

        // O += P V  (rows ty*4+i, cols tx*4+j)
        #pragma unroll
        for (int c = 0; c < 32; c += 4) {
            float4 v0 = *(const float4*)&Vs[(c + 0) * 68 + tx * 4];
            float4 v1 = *(const float4*)&Vs[(c + 1) * 68 + tx * 4];
            float4 v2 = *(const float4*)&Vs[(c + 2) * 68 + tx * 4];
            float4 v3 = *(const float4*)&Vs[(c + 3) * 68 + tx * 4];
            #pragma unroll
            for (int i = 0; i < 4; i++) {
                float4 p = *(const float4*)&Ss[(ty * 4 + i) * 36 + c];
                o[i][0] += p.x * v0.x + p.y * v1.x + p.z * v2.x + p.w * v3.x;
                o[i][1] += p.x * v0.y + p.y * v1.y + p.z * v2.y + p.w * v3.y;
                o[i][2] += p.x * v0.z + p.y * v1.z + p.z * v2.z + p.w * v3.z;
                o[i][3] += p.x * v0.w + p.y * v1.w + p.z * v2.w + p.w * v3.w;
            }
        }
        __syncthreads();
    }

    // normalize and write to [B,N,H*d]
    #pragma unroll
    for (int i = 0; i < 4; i++) {
        const int n = q0 + ty * 4 + i;
        const float inv = 1.0f / l[i];
        #pragma unroll
        for (int j = 0; j < 4; j++) {
            const int dd = tx * 4 + j;
            g_oh[((size_t)(b * N_ + n)) * INNER_ + h * D_ + dd] = o[i][j] * inv;
        }
    }
}

// ---------------------------------------------------------------------------
// K4: output GEMM.  g_oh[M,512] @ w_out[512,512] + b_out -> out[M,512]
// ---------------------------------------------------------------------------
__global__ __launch_bounds__(256) void gemm_out_kernel(
    const float* __restrict__ w, const float* __restrict__ bias,
    float* __restrict__ out)
{
    __shared__ float As[16 * 68];
    __shared__ float Bs[16 * 68];

    const int tid = threadIdx.x;
    const int ty = tid >> 4;
    const int tx = tid & 15;
    const int m0 = blockIdx.y * 64;
    const int n0 = blockIdx.x * 64;

    float acc[4][4] = {};

    for (int k0 = 0; k0 < INNER_; k0 += 16) {
        {
            const int r = tid >> 4, c = tid & 15;
            #pragma unroll
            for (int p = 0; p < 4; p++) {
                int rr = r + p * 16;
                As[c * 68 + rr] = g_oh[(size_t)(m0 + rr) * INNER_ + k0 + c];
            }
        }
        {
            const int r2 = tid >> 6, c2 = tid & 63;
            #pragma unroll
            for (int p = 0; p < 4; p++) {
                int rr = r2 + p * 4;
                Bs[rr * 68 + c2] = w[(size_t)(k0 + rr) * C_ + n0 + c2];
            }
        }
        __syncthreads();

        #pragma unroll
        for (int k = 0; k < 16; k++) {
            float4 a = *(const float4*)&As[k * 68 + ty * 4];
            float4 b = *(const float4*)&Bs[k * 68 + tx * 4];
            float av[4] = {a.x, a.y, a.z, a.w};
            float bv[4] = {b.x, b.y, b.z, b.w};
            #pragma unroll
            for (int i = 0; i < 4; i++)
                #pragma unroll
                for (int j = 0; j < 4; j++)
                    acc[i][j] += av[i] * bv[j];
        }
        __syncthreads();
    }

    #pragma unroll
    for (int i = 0; i < 4; i++) {
        const int row = m0 + ty * 4 + i;
        #pragma unroll
        for (int j = 0; j < 4; j++) {
            const int col = n0 + tx * 4 + j;
            out[(size_t)row * C_ + col] = acc[i][j] + bias[col];
        }
    }
}

// ---------------------------------------------------------------------------
extern "C" void kernel_launch(void* const* d_in, const int* in_sizes, int n_in,
                              void* d_out, int out_size)
{
    const float* x     = (const float*)d_in[0];  // [B,N,C]
    const float* pos   = (const float*)d_in[1];  // [N,D]
    const float* w_qkv = (const float*)d_in[2];  // [C, 3*inner]
    const float* w_out = (const float*)d_in[3];  // [inner, C]
    const float* b_out = (const float*)d_in[4];  // [C]
    float* out = (float*)d_out;

    // K1: QKV GEMM
    gemm_qkv_kernel<<<dim3(QKVCOLS_ / 64, M_ / 64), 256>>>(x, w_qkv);

    // K2: RoPE on q and k
    {
        const long total = (long)B_ * H_ * N_ * (D_ / 2);
        const int blocks = (int)((total + 255) / 256);
        rope_kernel<<<blocks, 256>>>(pos, 0);
        rope_kernel<<<blocks, 256>>>(pos, 1);
    }

    // K3: fused attention
    flash_kernel<<<dim3(N_ / 64, B_ * H_), 256>>>();

    // K4: output projection + bias
    gemm_out_kernel<<<dim3(C_ / 64, M_ / 64), 256>>>(w_out, b_out, out);
}

// round 2
// speedup vs baseline: 2.2962x; 2.2962x over previous
#include <cuda_runtime.h>
#include <cuda_bf16.h>
#include <cstdint>

// Problem constants
#define B_   2
#define N_   4096
#define C_   512
#define H_   8
#define D_   64
#define INNER_ (H_ * D_)          // 512
#define QKVCOLS_ (INNER_ * 3)     // 1536
#define M_ (B_ * N_)              // 8192

// Scratch (device globals; no cudaMalloc allowed)
__device__ float g_q[B_ * H_ * N_ * D_];   // 16 MB
__device__ float g_k[B_ * H_ * N_ * D_];   // 16 MB
__device__ float g_v[B_ * H_ * N_ * D_];   // 16 MB
__device__ float g_oh[B_ * N_ * INNER_];   // 16 MB, [B,N,H*d]

// ---------------------------------------------------------------------------
// K1: QKV GEMM.  x[M,512] @ w[512,1536] -> scatter into g_q/g_k/g_v [B,H,N,d]
// ---------------------------------------------------------------------------
__global__ __launch_bounds__(256) void gemm_qkv_kernel(
    const float* __restrict__ x, const float* __restrict__ w)
{
    __shared__ float As[16 * 68];
    __shared__ float Bs[16 * 68];

    const int tid = threadIdx.x;
    const int ty = tid >> 4;
    const int tx = tid & 15;
    const int m0 = blockIdx.y * 64;
    const int n0 = blockIdx.x * 64;

    float acc[4][4] = {};

    for (int k0 = 0; k0 < C_; k0 += 16) {
        {
            const int r = tid >> 4, c = tid & 15;
            #pragma unroll
            for (int p = 0; p < 4; p++) {
                int rr = r + p * 16;
                As[c * 68 + rr] = x[(size_t)(m0 + rr) * C_ + k0 + c];
            }
        }
        {
            const int r2 = tid >> 6, c2 = tid & 63;
            #pragma unroll
            for (int p = 0; p < 4; p++) {
                int rr = r2 + p * 4;
                Bs[rr * 68 + c2] = w[(size_t)(k0 + rr) * QKVCOLS_ + n0 + c2];
            }
        }
        __syncthreads();

        #pragma unroll
        for (int k = 0; k < 16; k++) {
            float4 a = *(const float4*)&As[k * 68 + ty * 4];
            float4 b = *(const float4*)&Bs[k * 68 + tx * 4];
            float av[4] = {a.x, a.y, a.z, a.w};
            float bv[4] = {b.x, b.y, b.z, b.w};
            #pragma unroll
            for (int i = 0; i < 4; i++)
                #pragma unroll
                for (int j = 0; j < 4; j++)
                    acc[i][j] += av[i] * bv[j];
        }
        __syncthreads();
    }

    #pragma unroll
    for (int i = 0; i < 4; i++) {
        const int row = m0 + ty * 4 + i;
        const int b = row >> 12;
        const int n = row & (N_ - 1);
        #pragma unroll
        for (int j = 0; j < 4; j++) {
            const int col = n0 + tx * 4 + j;
            const int part = col >> 9;
            const int rem = col & 511;
            const int h = rem >> 6;
            const int dd = rem & 63;
            size_t idx = ((size_t)(b * H_ + h) * N_ + n) * D_ + dd;
            float* dst = (part == 0) ? g_q : (part == 1) ? g_k : g_v;
            dst[idx] = acc[i][j];
        }
    }
}

// ---------------------------------------------------------------------------
// K2: RoPE in-place on g_q or g_k.
// ---------------------------------------------------------------------------
__global__ __launch_bounds__(256) void rope_kernel(
    const float* __restrict__ pos, int which)
{
    float* buf = (which == 0) ? g_q : g_k;
    const long total = (long)B_ * H_ * N_ * (D_ / 2);
    long i = (long)blockIdx.x * blockDim.x + threadIdx.x;
    if (i >= total) return;
    const int half = (int)(i & 31);
    const long rest = i >> 5;
    const int n = (int)(rest & (N_ - 1));
    const long base = rest << 6;

    const float p1 = pos[n * D_ + half];
    const float p2 = pos[n * D_ + half + 32];
    const float t1 = buf[base + half];
    const float t2 = buf[base + half + 32];
    buf[base + half]      = t1 * cosf(p1) - t2 * sinf(p1);
    buf[base + half + 32] = t2 * cosf(p2) + t1 * sinf(p2);
}

// ---------------------------------------------------------------------------
// K3: flash attention with mma.sync bf16 split-precision (hi/lo).
// BR=128 q rows/block, BC=32 kv/tile, 8 warps; warp = 16 q-rows x full kv.
// ---------------------------------------------------------------------------
#define BR 128
#define BC 32
#define SCALE_LOG2E (0.125f * 1.4426950408889634f)

struct __align__(128) FlashSmem {
    __nv_bfloat16 qhi[BR * 64];   // 16 KB
    __nv_bfloat16 qlo[BR * 64];   // 16 KB
    __nv_bfloat16 khi[BC * 64];   //  4 KB
    __nv_bfloat16 klo[BC * 64];
    __nv_bfloat16 vhi[BC * 64];
    __nv_bfloat16 vlo[BC * 64];
};                                // 48 KB total

// swizzled byte offset inside a [rows][64] bf16 tile (128B rows)
__device__ __forceinline__ uint32_t swz(uint32_t row, uint32_t col)
{
    uint32_t b = (row << 7) + (col << 1);
    return b ^ ((b >> 3) & 0x70);
}

__device__ __forceinline__ uint32_t u32bf2(__nv_bfloat162 v)
{
    return reinterpret_cast<uint32_t&>(v);
}

__device__ __forceinline__ void ldsm4(uint32_t a[4], uint32_t addr)
{
    asm volatile("ldmatrix.sync.aligned.m8n8.x4.shared.b16 {%0,%1,%2,%3}, [%4];"
                 : "=r"(a[0]), "=r"(a[1]), "=r"(a[2]), "=r"(a[3]) : "r"(addr));
}
__device__ __forceinline__ void ldsm2(uint32_t& b0, uint32_t& b1, uint32_t addr)
{
    asm volatile("ldmatrix.sync.aligned.m8n8.x2.shared.b16 {%0,%1}, [%2];"
                 : "=r"(b0), "=r"(b1) : "r"(addr));
}
__device__ __forceinline__ void ldsm2t(uint32_t& b0, uint32_t& b1, uint32_t addr)
{
    asm volatile("ldmatrix.sync.aligned.m8n8.x2.trans.shared.b16 {%0,%1}, [%2];"
                 : "=r"(b0), "=r"(b1) : "r"(addr));
}
__device__ __forceinline__ void mma16816(float c[4], const uint32_t a[4],
                                         uint32_t b0, uint32_t b1)
{
    asm volatile(
        "mma.sync.aligned.m16n8k16.row.col.f32.bf16.bf16.f32 "
        "{%0,%1,%2,%3}, {%4,%5,%6,%7}, {%8,%9}, {%0,%1,%2,%3};"
        : "+f"(c[0]), "+f"(c[1]), "+f"(c[2]), "+f"(c[3])
        : "r"(a[0]), "r"(a[1]), "r"(a[2]), "r"(a[3]), "r"(b0), "r"(b1));
}

// convert a float4 to bf16 hi/lo and store 8B to each tile at swizzled offset
__device__ __forceinline__ void cvt_store(float4 f, char* hib, char* lob,
                                          uint32_t off)
{
    __nv_bfloat162 h0 = __floats2bfloat162_rn(f.x, f.y);
    __nv_bfloat162 h1 = __floats2bfloat162_rn(f.z, f.w);
    float2 h0f = __bfloat1622float2(h0);
    float2 h1f = __bfloat1622float2(h1);
    __nv_bfloat162 l0 = __floats2bfloat162_rn(f.x - h0f.x, f.y - h0f.y);
    __nv_bfloat162 l1 = __floats2bfloat162_rn(f.z - h1f.x, f.w - h1f.y);
    *(uint2*)(hib + off) = make_uint2(u32bf2(h0), u32bf2(h1));
    *(uint2*)(lob + off) = make_uint2(u32bf2(l0), u32bf2(l1));
}

__global__ __launch_bounds__(256) void flash_mma_kernel()
{
    __shared__ FlashSmem sm;

    const int tid = threadIdx.x;
    const int wid = tid >> 5;
    const int lane = tid & 31;
    const int bh = blockIdx.y;
    const int b = bh >> 3, h = bh & 7;
    const int q0 = blockIdx.x * BR;

    const uint32_t s_qhi = (uint32_t)__cvta_generic_to_shared(sm.qhi);
    const uint32_t s_qlo = (uint32_t)__cvta_generic_to_shared(sm.qlo);
    const uint32_t s_khi = (uint32_t)__cvta_generic_to_shared(sm.khi);
    const uint32_t s_klo = (uint32_t)__cvta_generic_to_shared(sm.klo);
    const uint32_t s_vhi = (uint32_t)__cvta_generic_to_shared(sm.vhi);
    const uint32_t s_vlo = (uint32_t)__cvta_generic_to_shared(sm.vlo);

    // ---- stage Q (scaled by 1/sqrt(d) * log2(e)), split hi/lo ----
    {
        const size_t qbase = ((size_t)bh * N_ + q0) * D_;
        #pragma unroll
        for (int i = 0; i < 8; i++) {
            int c = tid + i * 256;            // 0..2047 float4 chunks
            int row = c >> 4;
            int col = (c & 15) << 2;
            float4 f = *(const float4*)&g_q[qbase + (size_t)row * D_ + col];
            f.x *= SCALE_LOG2E; f.y *= SCALE_LOG2E;
            f.z *= SCALE_LOG2E; f.w *= SCALE_LOG2E;
            cvt_store(f, (char*)sm.qhi, (char*)sm.qlo, swz(row, col));
        }
    }
    __syncthreads();

    // ---- Q fragments (held in registers for the whole kernel) ----
    const int m0 = wid * 16;                  // warp's q-row base (in tile)
    uint32_t qh[4][4], ql[4][4];
    {
        int r = m0 + (lane & 15);
        #pragma unroll
        for (int t = 0; t < 4; t++) {
            int kc = t * 16 + ((lane & 16) ? 8 : 0);
            ldsm4(qh[t], s_qhi + swz(r, kc));
            ldsm4(ql[t], s_qlo + swz(r, kc));
        }
    }

    float o[8][4] = {};
    float mrow0 = -1e30f, mrow1 = -1e30f;
    float lrow0 = 0.f, lrow1 = 0.f;

    for (int kt = 0; kt < N_ / BC; kt++) {
        __syncthreads();                      // protect K/V smem reuse

        // ---- stage K,V tile (split hi/lo) ----
        const size_t kvbase = ((size_t)bh * N_ + (size_t)kt * BC) * D_;
        #pragma unroll
        for (int i = 0; i < 2; i++) {
            int c = tid + i * 256;            // 0..511 float4 chunks
            int row = c >> 4;
            int col = (c & 15) << 2;
            uint32_t off = swz(row, col);
            float4 fk = *(const float4*)&g_k[kvbase + (size_t)row * D_ + col];
            cvt_store(fk, (char*)sm.khi, (char*)sm.klo, off);
            float4 fv = *(const float4*)&g_v[kvbase + (size_t)row * D_ + col];
            cvt_store(fv, (char*)sm.vhi, (char*)sm.vlo, off);
        }
        __syncthreads();

        // ---- S = Q K^T (split: qh*kh + ql*kh + qh*kl) ----
        float s[4][4] = {};
        {
            int rr = (lane & 7);
            int cadd = (lane & 8);            // 0 or 8
            #pragma unroll
            for (int ni = 0; ni < 4; ni++) {
                #pragma unroll
                for (int t = 0; t < 4; t++) {
                    uint32_t kh0, kh1, kl0, kl1;
                    uint32_t offk = swz(ni * 8 + rr, t * 16 + cadd);
                    ldsm2(kh0, kh1, s_khi + offk);
                    ldsm2(kl0, kl1, s_klo + offk);
                    mma16816(s[ni], qh[t], kh0, kh1);
                    mma16816(s[ni], ql[t], kh0, kh1);
                    mma16816(s[ni], qh[t], kl0, kl1);
                }
            }
        }

        // ---- online softmax (base-2 domain) ----
        float rmax0 = -1e30f, rmax1 = -1e30f;
        #pragma unroll
        for (int ni = 0; ni < 4; ni++) {
            rmax0 = fmaxf(rmax0, fmaxf(s[ni][0], s[ni][1]));
            rmax1 = fmaxf(rmax1, fmaxf(s[ni][2], s[ni][3]));
        }
        rmax0 = fmaxf(rmax0, __shfl_xor_sync(0xffffffffu, rmax0, 1));
        rmax0 = fmaxf(rmax0, __shfl_xor_sync(0xffffffffu, rmax0, 2));
        rmax1 = fmaxf(rmax1, __shfl_xor_sync(0xffffffffu, rmax1, 1));
        rmax1 = fmaxf(rmax1, __shfl_xor_sync(0xffffffffu, rmax1, 2));

        const float mn0 = fmaxf(mrow0, rmax0);
        const float mn1 = fmaxf(mrow1, rmax1);
        const float a0 = exp2f(mrow0 - mn0);
        const float a1 = exp2f(mrow1 - mn1);
        mrow0 = mn0; mrow1 = mn1;

        float sum0 = 0.f, sum1 = 0.f;
        #pragma unroll
        for (int ni = 0; ni < 4; ni++) {
            s[ni][0] = exp2f(s[ni][0] - mn0);
            s[ni][1] = exp2f(s[ni][1] - mn0);
            s[ni][2] = exp2f(s[ni][2] - mn1);
            s[ni][3] = exp2f(s[ni][3] - mn1);
            sum0 += s[ni][0] + s[ni][1];
            sum1 += s[ni][2] + s[ni][3];
        }
        sum0 += __shfl_xor_sync(0xffffffffu, sum0, 1);
        sum0 += __shfl_xor_sync(0xffffffffu, sum0, 2);
        sum1 += __shfl_xor_sync(0xffffffffu, sum1, 1);
        sum1 += __shfl_xor_sync(0xffffffffu, sum1, 2);
        lrow0 = lrow0 * a0 + sum0;
        lrow1 = lrow1 * a1 + sum1;

        #pragma unroll
        for (int ni = 0; ni < 8; ni++) {
            o[ni][0] *= a0; o[ni][1] *= a0;
            o[ni][2] *= a1; o[ni][3] *= a1;
        }

        // ---- O += P V (split: ph*vh + pl*vh + ph*vl) ----
        #pragma unroll
        for (int t = 0; t < 2; t++) {
            // repack S accum frags [2t],[2t+1] as A-operand (hi/lo)
            uint32_t ah[4], al[4];
            {
                const float* p0 = s[2 * t];
                const float* p1 = s[2 * t + 1];
                __nv_bfloat162 h;
                float2 hf;
                h = __floats2bfloat162_rn(p0[0], p0[1]); hf = __bfloat1622float2(h);
                ah[0] = u32bf2(h);
                al[0] = u32bf2(__floats2bfloat162_rn(p0[0] - hf.x, p0[1] - hf.y));
                h = __floats2bfloat162_rn(p0[2], p0[3]); hf = __bfloat1622float2(h);
                ah[1] = u32bf2(h);
                al[1] = u32bf2(__floats2bfloat162_rn(p0[2] - hf.x, p0[3] - hf.y));
                h = __floats2bfloat162_rn(p1[0], p1[1]); hf = __bfloat1622float2(h);
                ah[2] = u32bf2(h);
                al[2] = u32bf2(__floats2bfloat162_rn(p1[0] - hf.x, p1[1] - hf.y));
                h = __floats2bfloat162_rn(p1[2], p1[3]); hf = __bfloat1622float2(h);
                ah[3] = u32bf2(h);
                al[3] = u32bf2(__floats2bfloat162_rn(p1[2] - hf.x, p1[3] - hf.y));
            }
            int rr = t * 16 + (lane & 15);
            #pragma unroll
            for (int ni = 0; ni < 8; ni++) {
                uint32_t vh0, vh1, vl0, vl1;
                uint32_t offv = swz(rr, ni * 8);
                ldsm2t(vh0, vh1, s_vhi + offv);
                ldsm2t(vl0, vl1, s_vlo + offv);
                mma16816(o[ni], ah, vh0, vh1);
                mma16816(o[ni], al, vh0, vh1);
                mma16816(o[ni], ah, vl0, vl1);
            }
        }
    }

    // ---- normalize + write O to [B,N,H*d] ----
    {
        const float inv0 = 1.0f / lrow0;
        const float inv1 = 1.0f / lrow1;
        const int r0 = q0 + m0 + (lane >> 2);
        const int cb = 2 * (lane & 3);
        const size_t base0 = ((size_t)(b * N_ + r0)) * INNER_ + h * D_;
        const size_t base1 = ((size_t)(b * N_ + r0 + 8)) * INNER_ + h * D_;
        #pragma unroll
        for (int ni = 0; ni < 8; ni++) {
            int dd = ni * 8 + cb;
            *(float2*)&g_oh[base0 + dd] = make_float2(o[ni][0] * inv0,
                                                      o[ni][1] * inv0);
            *(float2*)&g_oh[base1 + dd] = make_float2(o[ni][2] * inv1,
                                                      o[ni][3] * inv1);
        }
    }
}

// ---------------------------------------------------------------------------
// K4: output GEMM.  g_oh[M,512] @ w_out[512,512] + b_out -> out[M,512]
// ---------------------------------------------------------------------------
__global__ __launch_bounds__(256) void gemm_out_kernel(
    const float* __restrict__ w, const float* __restrict__ bias,
    float* __restrict__ out)
{
    __shared__ float As[16 * 68];
    __shared__ float Bs[16 * 68];

    const int tid = threadIdx.x;
    const int ty = tid >> 4;
    const int tx = tid & 15;
    const int m0 = blockIdx.y * 64;
    const int n0 = blockIdx.x * 64;

    float acc[4][4] = {};

    for (int k0 = 0; k0 < INNER_; k0 += 16) {
        {
            const int r = tid >> 4, c = tid & 15;
            #pragma unroll
            for (int p = 0; p < 4; p++) {
                int rr = r + p * 16;
                As[c * 68 + rr] = g_oh[(size_t)(m0 + rr) * INNER_ + k0 + c];
            }
        }
        {
            const int r2 = tid >> 6, c2 = tid & 63;
            #pragma unroll
            for (int p = 0; p < 4; p++) {
                int rr = r2 + p * 4;
                Bs[rr * 68 + c2] = w[(size_t)(k0 + rr) * C_ + n0 + c2];
            }
        }
        __syncthreads();

        #pragma unroll
        for (int k = 0; k < 16; k++) {
            float4 a = *(const float4*)&As[k * 68 + ty * 4];
            float4 b = *(const float4*)&Bs[k * 68 + tx * 4];
            float av[4] = {a.x, a.y, a.z, a.w};
            float bv[4] = {b.x, b.y, b.z, b.w};
            #pragma unroll
            for (int i = 0; i < 4; i++)
                #pragma unroll
                for (int j = 0; j < 4; j++)
                    acc[i][j] += av[i] * bv[j];
        }
        __syncthreads();
    }

    #pragma unroll
    for (int i = 0; i < 4; i++) {
        const int row = m0 + ty * 4 + i;
        #pragma unroll
        for (int j = 0; j < 4; j++) {
            const int col = n0 + tx * 4 + j;
            out[(size_t)row * C_ + col] = acc[i][j] + bias[col];
        }
    }
}

// ---------------------------------------------------------------------------
extern "C" void kernel_launch(void* const* d_in, const int* in_sizes, int n_in,
                              void* d_out, int out_size)
{
    const float* x     = (const float*)d_in[0];
    const float* pos   = (const float*)d_in[1];
    const float* w_qkv = (const float*)d_in[2];
    const float* w_out = (const float*)d_in[3];
    const float* b_out = (const float*)d_in[4];
    float* out = (float*)d_out;

    gemm_qkv_kernel<<<dim3(QKVCOLS_ / 64, M_ / 64), 256>>>(x, w_qkv);

    {
        const long total = (long)B_ * H_ * N_ * (D_ / 2);
        const int blocks = (int)((total + 255) / 256);
        rope_kernel<<<blocks, 256>>>(pos, 0);
        rope_kernel<<<blocks, 256>>>(pos, 1);
    }

    flash_mma_kernel<<<dim3(N_ / BR, B_ * H_), 256>>>();

    gemm_out_kernel<<<dim3(C_ / 64, M_ / 64), 256>>>(w_out, b_out, out);
}

// round 3
// speedup vs baseline: 2.8163x; 1.2265x over previous
#include <cuda_runtime.h>
#include <cuda_bf16.h>
#include <cstdint>

// Problem constants
#define B_   2
#define N_   4096
#define C_   512
#define H_   8
#define D_   64
#define INNER_ (H_ * D_)          // 512
#define QKVCOLS_ (INNER_ * 3)     // 1536
#define M_ (B_ * N_)              // 8192
#define R_TOTAL (B_ * H_ * N_)    // 65536 rows of 64

// Scratch (device globals; no cudaMalloc allowed)
__device__ float g_q[B_ * H_ * N_ * D_];
__device__ float g_k[B_ * H_ * N_ * D_];
__device__ float g_v[B_ * H_ * N_ * D_];
__device__ float g_oh[B_ * N_ * INNER_];
// bf16 hi/lo split versions (post-RoPE, q pre-scaled)
__device__ __nv_bfloat16 g_qh[R_TOTAL * D_], g_ql[R_TOTAL * D_];
__device__ __nv_bfloat16 g_kh[R_TOTAL * D_], g_kl[R_TOTAL * D_];
__device__ __nv_bfloat16 g_vh[R_TOTAL * D_], g_vl[R_TOTAL * D_];

#define SCALE_LOG2E (0.125f * 1.4426950408889634f)

// ---------------------------------------------------------------------------
// K1: QKV GEMM.  x[M,512] @ w[512,1536] -> scatter into g_q/g_k/g_v [B,H,N,d]
// ---------------------------------------------------------------------------
__global__ __launch_bounds__(256) void gemm_qkv_kernel(
    const float* __restrict__ x, const float* __restrict__ w)
{
    __shared__ float As[16 * 68];
    __shared__ float Bs[16 * 68];

    const int tid = threadIdx.x;
    const int ty = tid >> 4;
    const int tx = tid & 15;
    const int m0 = blockIdx.y * 64;
    const int n0 = blockIdx.x * 64;

    float acc[4][4] = {};

    for (int k0 = 0; k0 < C_; k0 += 16) {
        {
            const int r = tid >> 4, c = tid & 15;
            #pragma unroll
            for (int p = 0; p < 4; p++) {
                int rr = r + p * 16;
                As[c * 68 + rr] = x[(size_t)(m0 + rr) * C_ + k0 + c];
            }
        }
        {
            const int r2 = tid >> 6, c2 = tid & 63;
            #pragma unroll
            for (int p = 0; p < 4; p++) {
                int rr = r2 + p * 4;
                Bs[rr * 68 + c2] = w[(size_t)(k0 + rr) * QKVCOLS_ + n0 + c2];
            }
        }
        __syncthreads();

        #pragma unroll
        for (int k = 0; k < 16; k++) {
            float4 a = *(const float4*)&As[k * 68 + ty * 4];
            float4 b = *(const float4*)&Bs[k * 68 + tx * 4];
            float av[4] = {a.x, a.y, a.z, a.w};
            float bv[4] = {b.x, b.y, b.z, b.w};
            #pragma unroll
            for (int i = 0; i < 4; i++)
                #pragma unroll
                for (int j = 0; j < 4; j++)
                    acc[i][j] += av[i] * bv[j];
        }
        __syncthreads();
    }

    #pragma unroll
    for (int i = 0; i < 4; i++) {
        const int row = m0 + ty * 4 + i;
        const int b = row >> 12;
        const int n = row & (N_ - 1);
        #pragma unroll
        for (int j = 0; j < 4; j++) {
            const int col = n0 + tx * 4 + j;
            const int part = col >> 9;
            const int rem = col & 511;
            const int h = rem >> 6;
            const int dd = rem & 63;
            size_t idx = ((size_t)(b * H_ + h) * N_ + n) * D_ + dd;
            float* dst = (part == 0) ? g_q : (part == 1) ? g_k : g_v;
            dst[idx] = acc[i][j];
        }
    }
}

// ---------------------------------------------------------------------------
// K2: prep — RoPE(q,k) + scale q + split all of q/k/v into bf16 hi/lo.
// One thread per (row, dd). 4 rows per 256-thread block.
// ---------------------------------------------------------------------------
__device__ __forceinline__ void split_store(float v, __nv_bfloat16* hi,
                                            __nv_bfloat16* lo, size_t idx)
{
    __nv_bfloat16 h = __float2bfloat16(v);
    hi[idx] = h;
    lo[idx] = __float2bfloat16(v - __bfloat162float(h));
}

__global__ __launch_bounds__(256) void prep_kernel(const float* __restrict__ pos)
{
    const int tid = threadIdx.x;
    const int row = blockIdx.x * 4 + (tid >> 6);
    const int dd = tid & 63;
    const int n = row & (N_ - 1);
    const size_t idx = (size_t)row * D_ + dd;

    float sn, cs;
    __sincosf(pos[n * D_ + dd], &sn, &cs);
    const int partner = dd ^ 32;
    const float sign = (dd < 32) ? -1.0f : 1.0f;

    // q: rope + scale
    {
        const float t = g_q[idx];
        const float tp = g_q[(size_t)row * D_ + partner];
        const float r = (t * cs + sign * tp * sn) * SCALE_LOG2E;
        split_store(r, g_qh, g_ql, idx);
    }
    // k: rope
    {
        const float t = g_k[idx];
        const float tp = g_k[(size_t)row * D_ + partner];
        const float r = t * cs + sign * tp * sn;
        split_store(r, g_kh, g_kl, idx);
    }
    // v: plain split
    split_store(g_v[idx], g_vh, g_vl, idx);
}

// ---------------------------------------------------------------------------
// K3: flash attention, bf16 split mma.sync, cp.async double-buffered K/V.
// BR=128, BC=32, 8 warps; warp owns 16 q-rows.
// ---------------------------------------------------------------------------
#define BR 128
#define BC 32
#define NT (N_ / BC)

// dynamic smem layout (bytes)
#define SQ_H  0
#define SQ_L  16384
#define SK_H  32768       // +buf*4096
#define SK_L  40960
#define SV_H  49152
#define SV_L  57344
#define SMEM_BYTES 65536

__device__ __forceinline__ uint32_t swz(uint32_t row, uint32_t colb)
{
    uint32_t b = (row << 7) + colb;     // 128B rows
    return b ^ ((b >> 3) & 0x70);
}
__device__ __forceinline__ uint32_t u32bf2(__nv_bfloat162 v)
{
    return reinterpret_cast<uint32_t&>(v);
}
__device__ __forceinline__ void cp16(uint32_t dst, const void* src)
{
    asm volatile("cp.async.cg.shared.global [%0], [%1], 16;"
                 :: "r"(dst), "l"(src));
}
__device__ __forceinline__ void cp_commit()
{
    asm volatile("cp.async.commit_group;");
}
__device__ __forceinline__ void cp_wait0()
{
    asm volatile("cp.async.wait_group 0;");
}
__device__ __forceinline__ void ldsm4(uint32_t a[4], uint32_t addr)
{
    asm volatile("ldmatrix.sync.aligned.m8n8.x4.shared.b16 {%0,%1,%2,%3}, [%4];"
                 : "=r"(a[0]), "=r"(a[1]), "=r"(a[2]), "=r"(a[3]) : "r"(addr));
}
__device__ __forceinline__ void ldsm4t(uint32_t a[4], uint32_t addr)
{
    asm volatile("ldmatrix.sync.aligned.m8n8.x4.trans.shared.b16 {%0,%1,%2,%3}, [%4];"
                 : "=r"(a[0]), "=r"(a[1]), "=r"(a[2]), "=r"(a[3]) : "r"(addr));
}
__device__ __forceinline__ void mma16816(float c[4], const uint32_t a[4],
                                         uint32_t b0, uint32_t b1)
{
    asm volatile(
        "mma.sync.aligned.m16n8k16.row.col.f32.bf16.bf16.f32 "
        "{%0,%1,%2,%3}, {%4,%5,%6,%7}, {%8,%9}, {%0,%1,%2,%3};"
        : "+f"(c[0]), "+f"(c[1]), "+f"(c[2]), "+f"(c[3])
        : "r"(a[0]), "r"(a[1]), "r"(a[2]), "r"(a[3]), "r"(b0), "r"(b1));
}

__global__ __launch_bounds__(256, 2) void flash_mma_kernel()
{
    extern __shared__ char smraw[];
    const uint32_t sb = (uint32_t)__cvta_generic_to_shared(smraw);

    const int tid = threadIdx.x;
    const int wid = tid >> 5;
    const int lane = tid & 31;
    const int bh = blockIdx.y;
    const int b = bh >> 3, h = bh & 7;
    const int q0 = blockIdx.x * BR;

    // ---- stage Q via cp.async (hi then lo) ----
    {
        const size_t qbase = ((size_t)bh * N_ + q0) * D_;
        #pragma unroll
        for (int i = 0; i < 8; i++) {
            int c = tid + i * 256;            // 0..2047
            int arr = c >> 10;                // 0=hi,1=lo
            int cc = c & 1023;
            int row = cc >> 3;
            int col16 = cc & 7;
            const __nv_bfloat16* src =
                (arr ? g_ql : g_qh) + qbase + (size_t)row * D_ + col16 * 8;
            cp16(sb + (arr ? SQ_L : SQ_H) + swz(row, col16 * 16), src);
        }
    }
    // ---- stage KV tile 0 into buffer 0 ----
    {
        const size_t kvbase = (size_t)bh * N_ * D_;
        #pragma unroll
        for (int i = 0; i < 4; i++) {
            int c = tid + i * 256;            // 0..1023
            int arr = c >> 8;                 // 0 kh,1 kl,2 vh,3 vl
            int cc = c & 255;
            int row = cc >> 3;
            int col16 = cc & 7;
            const __nv_bfloat16* base =
                (arr == 0) ? g_kh : (arr == 1) ? g_kl : (arr == 2) ? g_vh : g_vl;
            uint32_t soff = (arr == 0) ? SK_H : (arr == 1) ? SK_L
                          : (arr == 2) ? SV_H : SV_L;
            cp16(sb + soff + swz(row, col16 * 16),
                 base + kvbase + (size_t)row * D_ + col16 * 8);
        }
    }
    cp_commit();
    cp_wait0();
    __syncthreads();

    // ---- Q fragments (registers, whole kernel) ----
    const int m0 = wid * 16;
    uint32_t qh[4][4], ql[4][4];
    {
        int r = m0 + (lane & 15);
        int cadd = (lane & 16) ? 16 : 0;      // byte offset of +8 cols
        #pragma unroll
        for (int t = 0; t < 4; t++) {
            ldsm4(qh[t], sb + SQ_H + swz(r, t * 32 + cadd));
            ldsm4(ql[t], sb + SQ_L + swz(r, t * 32 + cadd));
        }
    }

    float o[8][4] = {};
    float mrow0 = -1e30f, mrow1 = -1e30f;
    float lrow0 = 0.f, lrow1 = 0.f;

    const size_t kvstride = (size_t)bh * N_ * D_;

    for (int kt = 0; kt < NT; kt++) {
        const uint32_t buf = (kt & 1) ? 4096 : 0;
        const uint32_t nbuf = (kt & 1) ? 0 : 4096;

        // prefetch next tile
        if (kt + 1 < NT) {
            const size_t kvbase = kvstride + (size_t)(kt + 1) * BC * D_;
            #pragma unroll
            for (int i = 0; i < 4; i++) {
                int c = tid + i * 256;
                int arr = c >> 8;
                int cc = c & 255;
                int row = cc >> 3;
                int col16 = cc & 7;
                const __nv_bfloat16* base =
                    (arr == 0) ? g_kh : (arr == 1) ? g_kl
                  : (arr == 2) ? g_vh : g_vl;
                uint32_t soff = (arr == 0) ? SK_H : (arr == 1) ? SK_L
                              : (arr == 2) ? SV_H : SV_L;
                cp16(sb + soff + nbuf + swz(row, col16 * 16),
                     base + kvbase + (size_t)row * D_ + col16 * 8);
            }
            cp_commit();
        }

        // ---- S = Q K^T (hi*hi + lo*hi + hi*lo) ----
        float s[4][4] = {};
        {
            const int rbase = lane & 15;
            const int cadd = (lane & 16) ? 16 : 0;
            #pragma unroll
            for (int p = 0; p < 2; p++) {
                #pragma unroll
                for (int t = 0; t < 4; t++) {
                    uint32_t KH[4], KL[4];
                    uint32_t off = swz(p * 16 + rbase, t * 32 + cadd);
                    ldsm4(KH, sb + SK_H + buf + off);
                    ldsm4(KL, sb + SK_L + buf + off);
                    mma16816(s[2 * p],     qh[t], KH[0], KH[2]);
                    mma16816(s[2 * p + 1], qh[t], KH[1], KH[3]);
                    mma16816(s[2 * p],     ql[t], KH[0], KH[2]);
                    mma16816(s[2 * p + 1], ql[t], KH[1], KH[3]);
                    mma16816(s[2 * p],     qh[t], KL[0], KL[2]);
                    mma16816(s[2 * p + 1], qh[t], KL[1], KL[3]);
                }
            }
        }

        // ---- online softmax (base-2) ----
        float rmax0 = -1e30f, rmax1 = -1e30f;
        #pragma unroll
        for (int ni = 0; ni < 4; ni++) {
            rmax0 = fmaxf(rmax0, fmaxf(s[ni][0], s[ni][1]));
            rmax1 = fmaxf(rmax1, fmaxf(s[ni][2], s[ni][3]));
        }
        rmax0 = fmaxf(rmax0, __shfl_xor_sync(0xffffffffu, rmax0, 1));
        rmax0 = fmaxf(rmax0, __shfl_xor_sync(0xffffffffu, rmax0, 2));
        rmax1 = fmaxf(rmax1, __shfl_xor_sync(0xffffffffu, rmax1, 1));
        rmax1 = fmaxf(rmax1, __shfl_xor_sync(0xffffffffu, rmax1, 2));

        const float mn0 = fmaxf(mrow0, rmax0);
        const float mn1 = fmaxf(mrow1, rmax1);
        const float a0 = exp2f(mrow0 - mn0);
        const float a1 = exp2f(mrow1 - mn1);
        mrow0 = mn0; mrow1 = mn1;

        float sum0 = 0.f, sum1 = 0.f;
        #pragma unroll
        for (int ni = 0; ni < 4; ni++) {
            s[ni][0] = exp2f(s[ni][0] - mn0);
            s[ni][1] = exp2f(s[ni][1] - mn0);
            s[ni][2] = exp2f(s[ni][2] - mn1);
            s[ni][3] = exp2f(s[ni][3] - mn1);
            sum0 += s[ni][0] + s[ni][1];
            sum1 += s[ni][2] + s[ni][3];
        }
        sum0 += __shfl_xor_sync(0xffffffffu, sum0, 1);
        sum0 += __shfl_xor_sync(0xffffffffu, sum0, 2);
        sum1 += __shfl_xor_sync(0xffffffffu, sum1, 1);
        sum1 += __shfl_xor_sync(0xffffffffu, sum1, 2);
        lrow0 = lrow0 * a0 + sum0;
        lrow1 = lrow1 * a1 + sum1;

        #pragma unroll
        for (int ni = 0; ni < 8; ni++) {
            o[ni][0] *= a0; o[ni][1] *= a0;
            o[ni][2] *= a1; o[ni][3] *= a1;
        }

        // ---- O += P V (hi*hi + lo*hi + hi*lo) ----
        #pragma unroll
        for (int t = 0; t < 2; t++) {
            uint32_t ah[4], al[4];
            {
                const float* p0 = s[2 * t];
                const float* p1 = s[2 * t + 1];
                __nv_bfloat162 hv; float2 hf;
                hv = __floats2bfloat162_rn(p0[0], p0[1]); hf = __bfloat1622float2(hv);
                ah[0] = u32bf2(hv);
                al[0] = u32bf2(__floats2bfloat162_rn(p0[0] - hf.x, p0[1] - hf.y));
                hv = __floats2bfloat162_rn(p0[2], p0[3]); hf = __bfloat1622float2(hv);
                ah[1] = u32bf2(hv);
                al[1] = u32bf2(__floats2bfloat162_rn(p0[2] - hf.x, p0[3] - hf.y));
                hv = __floats2bfloat162_rn(p1[0], p1[1]); hf = __bfloat1622float2(hv);
                ah[2] = u32bf2(hv);
                al[2] = u32bf2(__floats2bfloat162_rn(p1[0] - hf.x, p1[1] - hf.y));
                hv = __floats2bfloat162_rn(p1[2], p1[3]); hf = __bfloat1622float2(hv);
                ah[3] = u32bf2(hv);
                al[3] = u32bf2(__floats2bfloat162_rn(p1[2] - hf.x, p1[3] - hf.y));
            }
            const int rr = t * 16 + (lane & 15);
            const int cadd = (lane & 16) ? 16 : 0;
            #pragma unroll
            for (int dp = 0; dp < 4; dp++) {
                uint32_t VH[4], VL[4];
                uint32_t off = swz(rr, dp * 32 + cadd);
                ldsm4t(VH, sb + SV_H + buf + off);
                ldsm4t(VL, sb + SV_L + buf + off);
                mma16816(o[2 * dp],     ah, VH[0], VH[1]);
                mma16816(o[2 * dp + 1], ah, VH[2], VH[3]);
                mma16816(o[2 * dp],     al, VH[0], VH[1]);
                mma16816(o[2 * dp + 1], al, VH[2], VH[3]);
                mma16816(o[2 * dp],     ah, VL[0], VL[1]);
                mma16816(o[2 * dp + 1], ah, VL[2], VL[3]);
            }
        }

        cp_wait0();
        __syncthreads();
    }

    // ---- normalize + write O to [B,N,H*d] ----
    {
        const float inv0 = 1.0f / lrow0;
        const float inv1 = 1.0f / lrow1;
        const int r0 = q0 + m0 + (lane >> 2);
        const int cb = 2 * (lane & 3);
        const size_t base0 = ((size_t)(b * N_ + r0)) * INNER_ + h * D_;
        const size_t base1 = ((size_t)(b * N_ + r0 + 8)) * INNER_ + h * D_;
        #pragma unroll
        for (int ni = 0; ni < 8; ni++) {
            int dd = ni * 8 + cb;
            *(float2*)&g_oh[base0 + dd] = make_float2(o[ni][0] * inv0,
                                                      o[ni][1] * inv0);
            *(float2*)&g_oh[base1 + dd] = make_float2(o[ni][2] * inv1,
                                                      o[ni][3] * inv1);
        }
    }
}

// ---------------------------------------------------------------------------
// K4: output GEMM.  g_oh[M,512] @ w_out[512,512] + b_out -> out[M,512]
// ---------------------------------------------------------------------------
__global__ __launch_bounds__(256) void gemm_out_kernel(
    const float* __restrict__ w, const float* __restrict__ bias,
    float* __restrict__ out)
{
    __shared__ float As[16 * 68];
    __shared__ float Bs[16 * 68];

    const int tid = threadIdx.x;
    const int ty = tid >> 4;
    const int tx = tid & 15;
    const int m0 = blockIdx.y * 64;
    const int n0 = blockIdx.x * 64;

    float acc[4][4] = {};

    for (int k0 = 0; k0 < INNER_; k0 += 16) {
        {
            const int r = tid >> 4, c = tid & 15;
            #pragma unroll
            for (int p = 0; p < 4; p++) {
                int rr = r + p * 16;
                As[c * 68 + rr] = g_oh[(size_t)(m0 + rr) * INNER_ + k0 + c];
            }
        }
        {
            const int r2 = tid >> 6, c2 = tid & 63;
            #pragma unroll
            for (int p = 0; p < 4; p++) {
                int rr = r2 + p * 4;
                Bs[rr * 68 + c2] = w[(size_t)(k0 + rr) * C_ + n0 + c2];
            }
        }
        __syncthreads();

        #pragma unroll
        for (int k = 0; k < 16; k++) {
            float4 a = *(const float4*)&As[k * 68 + ty * 4];
            float4 b = *(const float4*)&Bs[k * 68 + tx * 4];
            float av[4] = {a.x, a.y, a.z, a.w};
            float bv[4] = {b.x, b.y, b.z, b.w};
            #pragma unroll
            for (int i = 0; i < 4; i++)
                #pragma unroll
                for (int j = 0; j < 4; j++)
                    acc[i][j] += av[i] * bv[j];
        }
        __syncthreads();
    }

    #pragma unroll
    for (int i = 0; i < 4; i++) {
        const int row = m0 + ty * 4 + i;
        #pragma unroll
        for (int j = 0; j < 4; j++) {
            const int col = n0 + tx * 4 + j;
            out[(size_t)row * C_ + col] = acc[i][j] + bias[col];
        }
    }
}

// ---------------------------------------------------------------------------
extern "C" void kernel_launch(void* const* d_in, const int* in_sizes, int n_in,
                              void* d_out, int out_size)
{
    const float* x     = (const float*)d_in[0];
    const float* pos   = (const float*)d_in[1];
    const float* w_qkv = (const float*)d_in[2];
    const float* w_out = (const float*)d_in[3];
    const float* b_out = (const float*)d_in[4];
    float* out = (float*)d_out;

    static bool attr_set = false;
    if (!attr_set) {
        cudaFuncSetAttribute(flash_mma_kernel,
                             cudaFuncAttributeMaxDynamicSharedMemorySize,
                             SMEM_BYTES);
        attr_set = true;
    }

    gemm_qkv_kernel<<<dim3(QKVCOLS_ / 64, M_ / 64), 256>>>(x, w_qkv);

    prep_kernel<<<R_TOTAL / 4, 256>>>(pos);

    flash_mma_kernel<<<dim3(N_ / BR, B_ * H_), 256, SMEM_BYTES>>>();

    gemm_out_kernel<<<dim3(C_ / 64, M_ / 64), 256>>>(w_out, b_out, out);
}

// round 4
// speedup vs baseline: 3.9684x; 1.4091x over previous
#include <cuda_runtime.h>
#include <cuda_bf16.h>
#include <cstdint>

// Problem constants
#define B_   2
#define N_   4096
#define C_   512
#define H_   8
#define D_   64
#define INNER_ (H_ * D_)          // 512
#define QKVCOLS_ (INNER_ * 3)     // 1536
#define M_ (B_ * N_)              // 8192
#define R_TOTAL (B_ * H_ * N_)    // 65536 rows of 64

// Scratch (device globals; no cudaMalloc allowed)
__device__ float g_q[B_ * H_ * N_ * D_];
__device__ float g_k[B_ * H_ * N_ * D_];
__device__ float g_v[B_ * H_ * N_ * D_];
// bf16 hi/lo split versions (post-RoPE, q pre-scaled)
__device__ __nv_bfloat16 g_qh[R_TOTAL * D_], g_ql[R_TOTAL * D_];
__device__ __nv_bfloat16 g_kh[R_TOTAL * D_], g_kl[R_TOTAL * D_];
__device__ __nv_bfloat16 g_vh[R_TOTAL * D_], g_vl[R_TOTAL * D_];
// bf16 split inputs for GEMMs
__device__ __nv_bfloat16 g_xh[M_ * C_], g_xl[M_ * C_];
__device__ __nv_bfloat16 g_wqh[C_ * QKVCOLS_], g_wql[C_ * QKVCOLS_];
__device__ __nv_bfloat16 g_woh[INNER_ * C_], g_wol[INNER_ * C_];
// attention output, bf16 split, [B,N,H*d]
__device__ __nv_bfloat16 g_ohh[B_ * N_ * INNER_], g_ohl[B_ * N_ * INNER_];

#define SCALE_LOG2E (0.125f * 1.4426950408889634f)

// ---------------------------------------------------------------------------
// common helpers
// ---------------------------------------------------------------------------
__device__ __forceinline__ uint32_t u32bf2(__nv_bfloat162 v)
{
    return reinterpret_cast<uint32_t&>(v);
}
// SW128 swizzle for 128B-row tiles
__device__ __forceinline__ uint32_t swz(uint32_t row, uint32_t colb)
{
    uint32_t b = (row << 7) + colb;
    return b ^ ((b >> 3) & 0x70);
}
// SW64 swizzle for 64B-row tiles
__device__ __forceinline__ uint32_t swzA(uint32_t row, uint32_t colb)
{
    uint32_t b = (row << 6) + colb;
    return b ^ ((b >> 3) & 0x30);
}
__device__ __forceinline__ void cp16(uint32_t dst, const void* src)
{
    asm volatile("cp.async.cg.shared.global [%0], [%1], 16;"
                 :: "r"(dst), "l"(src));
}
__device__ __forceinline__ void cp_commit()
{
    asm volatile("cp.async.commit_group;");
}
__device__ __forceinline__ void cp_wait0()
{
    asm volatile("cp.async.wait_group 0;");
}
__device__ __forceinline__ void cp_wait1()
{
    asm volatile("cp.async.wait_group 1;");
}
__device__ __forceinline__ void ldsm4(uint32_t a[4], uint32_t addr)
{
    asm volatile("ldmatrix.sync.aligned.m8n8.x4.shared.b16 {%0,%1,%2,%3}, [%4];"
                 : "=r"(a[0]), "=r"(a[1]), "=r"(a[2]), "=r"(a[3]) : "r"(addr));
}
__device__ __forceinline__ void ldsm4t(uint32_t a[4], uint32_t addr)
{
    asm volatile("ldmatrix.sync.aligned.m8n8.x4.trans.shared.b16 {%0,%1,%2,%3}, [%4];"
                 : "=r"(a[0]), "=r"(a[1]), "=r"(a[2]), "=r"(a[3]) : "r"(addr));
}
__device__ __forceinline__ void mma16816(float c[4], const uint32_t a[4],
                                         uint32_t b0, uint32_t b1)
{
    asm volatile(
        "mma.sync.aligned.m16n8k16.row.col.f32.bf16.bf16.f32 "
        "{%0,%1,%2,%3}, {%4,%5,%6,%7}, {%8,%9}, {%0,%1,%2,%3};"
        : "+f"(c[0]), "+f"(c[1]), "+f"(c[2]), "+f"(c[3])
        : "r"(a[0]), "r"(a[1]), "r"(a[2]), "r"(a[3]), "r"(b0), "r"(b1));
}

// ---------------------------------------------------------------------------
// K0: fp32 -> bf16 hi/lo split conversion
// ---------------------------------------------------------------------------
__global__ __launch_bounds__(256) void conv_split_kernel(
    const float4* __restrict__ src, uint2* __restrict__ hi,
    uint2* __restrict__ lo, int n4)
{
    int i = blockIdx.x * 256 + threadIdx.x;
    if (i >= n4) return;
    float4 f = src[i];
    __nv_bfloat162 h0 = __floats2bfloat162_rn(f.x, f.y);
    __nv_bfloat162 h1 = __floats2bfloat162_rn(f.z, f.w);
    float2 a = __bfloat1622float2(h0), b = __bfloat1622float2(h1);
    __nv_bfloat162 l0 = __floats2bfloat162_rn(f.x - a.x, f.y - a.y);
    __nv_bfloat162 l1 = __floats2bfloat162_rn(f.z - b.x, f.w - b.y);
    hi[i] = make_uint2(u32bf2(h0), u32bf2(h1));
    lo[i] = make_uint2(u32bf2(l0), u32bf2(l1));
}

// ---------------------------------------------------------------------------
// Tensor-core GEMM machinery: BM=128, BN=64, BK=32, 2-stage cp.async.
// 8 warps (4m x 2n), warp tile 32x32 via m16n8k16, bf16 hi/lo split (3 MMAs).
// ---------------------------------------------------------------------------
#define GSA_H 0
#define GSA_L 8192
#define GSB_H 16384
#define GSB_L 20480
#define GSTAGE 24576
#define GNKT (C_ / 32)   // 16

__device__ __forceinline__ void gemm_stage(
    uint32_t sb, uint32_t stg,
    const __nv_bfloat16* __restrict__ ah, const __nv_bfloat16* __restrict__ al,
    const __nv_bfloat16* __restrict__ bh, const __nv_bfloat16* __restrict__ bl,
    int m0, int n0, int k0, int ldb, int tid)
{
    #pragma unroll
    for (int i = 0; i < 6; i++) {
        int c = tid + i * 256;
        if (c < 512) {
            int row = c >> 2, col16 = c & 3;
            cp16(sb + stg + GSA_H + swzA(row, col16 * 16),
                 ah + (size_t)(m0 + row) * C_ + k0 + col16 * 8);
        } else if (c < 1024) {
            int cc = c - 512;
            int row = cc >> 2, col16 = cc & 3;
            cp16(sb + stg + GSA_L + swzA(row, col16 * 16),
                 al + (size_t)(m0 + row) * C_ + k0 + col16 * 8);
        } else if (c < 1280) {
            int cc = c - 1024;
            int row = cc >> 3, col16 = cc & 7;
            cp16(sb + stg + GSB_H + swz(row, col16 * 16),
                 bh + (size_t)(k0 + row) * ldb + n0 + col16 * 8);
        } else {
            int cc = c - 1280;
            int row = cc >> 3, col16 = cc & 7;
            cp16(sb + stg + GSB_L + swz(row, col16 * 16),
                 bl + (size_t)(k0 + row) * ldb + n0 + col16 * 8);
        }
    }
}

__device__ __forceinline__ void gemm_compute(
    uint32_t sb, uint32_t stg, float c[2][4][4], int wm, int wn, int lane)
{
    const int rA = lane & 15;
    const int cadd = (lane & 16) ? 16 : 0;
    #pragma unroll
    for (int t = 0; t < 2; t++) {
        uint32_t AH[2][4], AL[2][4], BH[2][4], BL[2][4];
        #pragma unroll
        for (int mi = 0; mi < 2; mi++) {
            uint32_t off = swzA(wm * 32 + mi * 16 + rA, t * 32 + cadd);
            ldsm4(AH[mi], sb + stg + GSA_H + off);
            ldsm4(AL[mi], sb + stg + GSA_L + off);
        }
        #pragma unroll
        for (int j2 = 0; j2 < 2; j2++) {
            uint32_t off = swz(t * 16 + rA, wn * 64 + j2 * 32 + cadd);
            ldsm4t(BH[j2], sb + stg + GSB_H + off);
            ldsm4t(BL[j2], sb + stg + GSB_L + off);
        }
        #pragma unroll
        for (int mi = 0; mi < 2; mi++) {
            #pragma unroll
            for (int j2 = 0; j2 < 2; j2++) {
                mma16816(c[mi][2 * j2],     AH[mi], BH[j2][0], BH[j2][1]);
                mma16816(c[mi][2 * j2 + 1], AH[mi], BH[j2][2], BH[j2][3]);
                mma16816(c[mi][2 * j2],     AL[mi], BH[j2][0], BH[j2][1]);
                mma16816(c[mi][2 * j2 + 1], AL[mi], BH[j2][2], BH[j2][3]);
                mma16816(c[mi][2 * j2],     AH[mi], BL[j2][0], BL[j2][1]);
                mma16816(c[mi][2 * j2 + 1], AH[mi], BL[j2][2], BL[j2][3]);
            }
        }
    }
}

// K1: QKV GEMM (tensor). grid (24, 64). Scatter fp32 into g_q/g_k/g_v [B,H,N,d].
__global__ __launch_bounds__(256) void gemm_qkv_mma()
{
    __shared__ char smem[2 * GSTAGE];
    const uint32_t sb = (uint32_t)__cvta_generic_to_shared(smem);
    const int tid = threadIdx.x;
    const int wid = tid >> 5, lane = tid & 31;
    const int wm = wid >> 1, wn = wid & 1;
    const int m0 = blockIdx.y * 128;
    const int n0 = blockIdx.x * 64;

    float c[2][4][4] = {};

    gemm_stage(sb, 0,      g_xh, g_xl, g_wqh, g_wql, m0, n0, 0,  QKVCOLS_, tid);
    cp_commit();
    gemm_stage(sb, GSTAGE, g_xh, g_xl, g_wqh, g_wql, m0, n0, 32, QKVCOLS_, tid);
    cp_commit();

    for (int kt = 0; kt < GNKT; kt++) {
        if (kt < GNKT - 1) cp_wait1(); else cp_wait0();
        __syncthreads();
        gemm_compute(sb, (kt & 1) * GSTAGE, c, wm, wn, lane);
        __syncthreads();
        if (kt + 2 < GNKT) {
            gemm_stage(sb, (kt & 1) * GSTAGE, g_xh, g_xl, g_wqh, g_wql,
                       m0, n0, (kt + 2) * 32, QKVCOLS_, tid);
            cp_commit();
        }
    }

    // epilogue: whole block writes one (part, head)
    const int part = n0 >> 9;
    const int h = (n0 & 511) >> 6;
    float* dst = (part == 0) ? g_q : (part == 1) ? g_k : g_v;
    #pragma unroll
    for (int mi = 0; mi < 2; mi++) {
        #pragma unroll
        for (int r8 = 0; r8 < 2; r8++) {
            const int mrow = m0 + wm * 32 + mi * 16 + r8 * 8 + (lane >> 2);
            const int b = mrow >> 12;
            const int n = mrow & (N_ - 1);
            const size_t base = ((size_t)(b * H_ + h) * N_ + n) * D_;
            #pragma unroll
            for (int nj = 0; nj < 4; nj++) {
                const int dd = wn * 32 + nj * 8 + (lane & 3) * 2;
                *(float2*)&dst[base + dd] =
                    make_float2(c[mi][nj][2 * r8], c[mi][nj][2 * r8 + 1]);
            }
        }
    }
}

// K4: output GEMM (tensor). grid (8, 64). out = OH @ w_out + bias.
__global__ __launch_bounds__(256) void gemm_out_mma(
    const float* __restrict__ bias, float* __restrict__ out)
{
    __shared__ char smem[2 * GSTAGE];
    const uint32_t sb = (uint32_t)__cvta_generic_to_shared(smem);
    const int tid = threadIdx.x;
    const int wid = tid >> 5, lane = tid & 31;
    const int wm = wid >> 1, wn = wid & 1;
    const int m0 = blockIdx.y * 128;
    const int n0 = blockIdx.x * 64;

    float c[2][4][4] = {};

    gemm_stage(sb, 0,      g_ohh, g_ohl, g_woh, g_wol, m0, n0, 0,  C_, tid);
    cp_commit();
    gemm_stage(sb, GSTAGE, g_ohh, g_ohl, g_woh, g_wol, m0, n0, 32, C_, tid);
    cp_commit();

    for (int kt = 0; kt < GNKT; kt++) {
        if (kt < GNKT - 1) cp_wait1(); else cp_wait0();
        __syncthreads();
        gemm_compute(sb, (kt & 1) * GSTAGE, c, wm, wn, lane);
        __syncthreads();
        if (kt + 2 < GNKT) {
            gemm_stage(sb, (kt & 1) * GSTAGE, g_ohh, g_ohl, g_woh, g_wol,
                       m0, n0, (kt + 2) * 32, C_, tid);
            cp_commit();
        }
    }

    #pragma unroll
    for (int mi = 0; mi < 2; mi++) {
        #pragma unroll
        for (int r8 = 0; r8 < 2; r8++) {
            const int mrow = m0 + wm * 32 + mi * 16 + r8 * 8 + (lane >> 2);
            #pragma unroll
            for (int nj = 0; nj < 4; nj++) {
                const int col = n0 + wn * 32 + nj * 8 + (lane & 3) * 2;
                *(float2*)&out[(size_t)mrow * C_ + col] =
                    make_float2(c[mi][nj][2 * r8] + bias[col],
                                c[mi][nj][2 * r8 + 1] + bias[col + 1]);
            }
        }
    }
}

// ---------------------------------------------------------------------------
// K2: prep — RoPE(q,k) + scale q + split q/k/v into bf16 hi/lo.
// ---------------------------------------------------------------------------
__device__ __forceinline__ void split_store(float v, __nv_bfloat16* hi,
                                            __nv_bfloat16* lo, size_t idx)
{
    __nv_bfloat16 h = __float2bfloat16(v);
    hi[idx] = h;
    lo[idx] = __float2bfloat16(v - __bfloat162float(h));
}

__global__ __launch_bounds__(256) void prep_kernel(const float* __restrict__ pos)
{
    const int tid = threadIdx.x;
    const int row = blockIdx.x * 4 + (tid >> 6);
    const int dd = tid & 63;
    const int n = row & (N_ - 1);
    const size_t idx = (size_t)row * D_ + dd;

    float sn, cs;
    __sincosf(pos[n * D_ + dd], &sn, &cs);
    const int partner = dd ^ 32;
    const float sign = (dd < 32) ? -1.0f : 1.0f;

    {
        const float t = g_q[idx];
        const float tp = g_q[(size_t)row * D_ + partner];
        const float r = (t * cs + sign * tp * sn) * SCALE_LOG2E;
        split_store(r, g_qh, g_ql, idx);
    }
    {
        const float t = g_k[idx];
        const float tp = g_k[(size_t)row * D_ + partner];
        const float r = t * cs + sign * tp * sn;
        split_store(r, g_kh, g_kl, idx);
    }
    split_store(g_v[idx], g_vh, g_vl, idx);
}

// ---------------------------------------------------------------------------
// K3: flash attention, bf16 split mma.sync, cp.async double-buffered K/V.
// ---------------------------------------------------------------------------
#define BR 128
#define BC 32
#define NT (N_ / BC)

#define SQ_H  0
#define SQ_L  16384
#define SK_H  32768
#define SK_L  40960
#define SV_H  49152
#define SV_L  57344
#define SMEM_BYTES 65536

__global__ __launch_bounds__(256, 2) void flash_mma_kernel()
{
    extern __shared__ char smraw[];
    const uint32_t sb = (uint32_t)__cvta_generic_to_shared(smraw);

    const int tid = threadIdx.x;
    const int wid = tid >> 5;
    const int lane = tid & 31;
    const int bh = blockIdx.y;
    const int b = bh >> 3, h = bh & 7;
    const int q0 = blockIdx.x * BR;

    {
        const size_t qbase = ((size_t)bh * N_ + q0) * D_;
        #pragma unroll
        for (int i = 0; i < 8; i++) {
            int c = tid + i * 256;
            int arr = c >> 10;
            int cc = c & 1023;
            int row = cc >> 3;
            int col16 = cc & 7;
            const __nv_bfloat16* src =
                (arr ? g_ql : g_qh) + qbase + (size_t)row * D_ + col16 * 8;
            cp16(sb + (arr ? SQ_L : SQ_H) + swz(row, col16 * 16), src);
        }
    }
    {
        const size_t kvbase = (size_t)bh * N_ * D_;
        #pragma unroll
        for (int i = 0; i < 4; i++) {
            int c = tid + i * 256;
            int arr = c >> 8;
            int cc = c & 255;
            int row = cc >> 3;
            int col16 = cc & 7;
            const __nv_bfloat16* base =
                (arr == 0) ? g_kh : (arr == 1) ? g_kl : (arr == 2) ? g_vh : g_vl;
            uint32_t soff = (arr == 0) ? SK_H : (arr == 1) ? SK_L
                          : (arr == 2) ? SV_H : SV_L;
            cp16(sb + soff + swz(row, col16 * 16),
                 base + kvbase + (size_t)row * D_ + col16 * 8);
        }
    }
    cp_commit();
    cp_wait0();
    __syncthreads();

    const int m0 = wid * 16;
    uint32_t qh[4][4], ql[4][4];
    {
        int r = m0 + (lane & 15);
        int cadd = (lane & 16) ? 16 : 0;
        #pragma unroll
        for (int t = 0; t < 4; t++) {
            ldsm4(qh[t], sb + SQ_H + swz(r, t * 32 + cadd));
            ldsm4(ql[t], sb + SQ_L + swz(r, t * 32 + cadd));
        }
    }

    float o[8][4] = {};
    float mrow0 = -1e30f, mrow1 = -1e30f;
    float lrow0 = 0.f, lrow1 = 0.f;

    const size_t kvstride = (size_t)bh * N_ * D_;

    for (int kt = 0; kt < NT; kt++) {
        const uint32_t buf = (kt & 1) ? 4096 : 0;
        const uint32_t nbuf = (kt & 1) ? 0 : 4096;

        if (kt + 1 < NT) {
            const size_t kvbase = kvstride + (size_t)(kt + 1) * BC * D_;
            #pragma unroll
            for (int i = 0; i < 4; i++) {
                int c = tid + i * 256;
                int arr = c >> 8;
                int cc = c & 255;
                int row = cc >> 3;
                int col16 = cc & 7;
                const __nv_bfloat16* base =
                    (arr == 0) ? g_kh : (arr == 1) ? g_kl
                  : (arr == 2) ? g_vh : g_vl;
                uint32_t soff = (arr == 0) ? SK_H : (arr == 1) ? SK_L
                              : (arr == 2) ? SV_H : SV_L;
                cp16(sb + soff + nbuf + swz(row, col16 * 16),
                     base + kvbase + (size_t)row * D_ + col16 * 8);
            }
            cp_commit();
        }

        float s[4][4] = {};
        {
            const int rbase = lane & 15;
            const int cadd = (lane & 16) ? 16 : 0;
            #pragma unroll
            for (int p = 0; p < 2; p++) {
                #pragma unroll
                for (int t = 0; t < 4; t++) {
                    uint32_t KH[4], KL[4];
                    uint32_t off = swz(p * 16 + rbase, t * 32 + cadd);
                    ldsm4(KH, sb + SK_H + buf + off);
                    ldsm4(KL, sb + SK_L + buf + off);
                    mma16816(s[2 * p],     qh[t], KH[0], KH[2]);
                    mma16816(s[2 * p + 1], qh[t], KH[1], KH[3]);
                    mma16816(s[2 * p],     ql[t], KH[0], KH[2]);
                    mma16816(s[2 * p + 1], ql[t], KH[1], KH[3]);
                    mma16816(s[2 * p],     qh[t], KL[0], KL[2]);
                    mma16816(s[2 * p + 1], qh[t], KL[1], KL[3]);
                }
            }
        }

        float rmax0 = -1e30f, rmax1 = -1e30f;
        #pragma unroll
        for (int ni = 0; ni < 4; ni++) {
            rmax0 = fmaxf(rmax0, fmaxf(s[ni][0], s[ni][1]));
            rmax1 = fmaxf(rmax1, fmaxf(s[ni][2], s[ni][3]));
        }
        rmax0 = fmaxf(rmax0, __shfl_xor_sync(0xffffffffu, rmax0, 1));
        rmax0 = fmaxf(rmax0, __shfl_xor_sync(0xffffffffu, rmax0, 2));
        rmax1 = fmaxf(rmax1, __shfl_xor_sync(0xffffffffu, rmax1, 1));
        rmax1 = fmaxf(rmax1, __shfl_xor_sync(0xffffffffu, rmax1, 2));

        const float mn0 = fmaxf(mrow0, rmax0);
        const float mn1 = fmaxf(mrow1, rmax1);
        const float a0 = exp2f(mrow0 - mn0);
        const float a1 = exp2f(mrow1 - mn1);
        mrow0 = mn0; mrow1 = mn1;

        float sum0 = 0.f, sum1 = 0.f;
        #pragma unroll
        for (int ni = 0; ni < 4; ni++) {
            s[ni][0] = exp2f(s[ni][0] - mn0);
            s[ni][1] = exp2f(s[ni][1] - mn0);
            s[ni][2] = exp2f(s[ni][2] - mn1);
            s[ni][3] = exp2f(s[ni][3] - mn1);
            sum0 += s[ni][0] + s[ni][1];
            sum1 += s[ni][2] + s[ni][3];
        }
        sum0 += __shfl_xor_sync(0xffffffffu, sum0, 1);
        sum0 += __shfl_xor_sync(0xffffffffu, sum0, 2);
        sum1 += __shfl_xor_sync(0xffffffffu, sum1, 1);
        sum1 += __shfl_xor_sync(0xffffffffu, sum1, 2);
        lrow0 = lrow0 * a0 + sum0;
        lrow1 = lrow1 * a1 + sum1;

        #pragma unroll
        for (int ni = 0; ni < 8; ni++) {
            o[ni][0] *= a0; o[ni][1] *= a0;
            o[ni][2] *= a1; o[ni][3] *= a1;
        }

        #pragma unroll
        for (int t = 0; t < 2; t++) {
            uint32_t ah[4], al[4];
            {
                const float* p0 = s[2 * t];
                const float* p1 = s[2 * t + 1];
                __nv_bfloat162 hv; float2 hf;
                hv = __floats2bfloat162_rn(p0[0], p0[1]); hf = __bfloat1622float2(hv);
                ah[0] = u32bf2(hv);
                al[0] = u32bf2(__floats2bfloat162_rn(p0[0] - hf.x, p0[1] - hf.y));
                hv = __floats2bfloat162_rn(p0[2], p0[3]); hf = __bfloat1622float2(hv);
                ah[1] = u32bf2(hv);
                al[1] = u32bf2(__floats2bfloat162_rn(p0[2] - hf.x, p0[3] - hf.y));
                hv = __floats2bfloat162_rn(p1[0], p1[1]); hf = __bfloat1622float2(hv);
                ah[2] = u32bf2(hv);
                al[2] = u32bf2(__floats2bfloat162_rn(p1[0] - hf.x, p1[1] - hf.y));
                hv = __floats2bfloat162_rn(p1[2], p1[3]); hf = __bfloat1622float2(hv);
                ah[3] = u32bf2(hv);
                al[3] = u32bf2(__floats2bfloat162_rn(p1[2] - hf.x, p1[3] - hf.y));
            }
            const int rr = t * 16 + (lane & 15);
            const int cadd = (lane & 16) ? 16 : 0;
            #pragma unroll
            for (int dp = 0; dp < 4; dp++) {
                uint32_t VH[4], VL[4];
                uint32_t off = swz(rr, dp * 32 + cadd);
                ldsm4t(VH, sb + SV_H + buf + off);
                ldsm4t(VL, sb + SV_L + buf + off);
                mma16816(o[2 * dp],     ah, VH[0], VH[1]);
                mma16816(o[2 * dp + 1], ah, VH[2], VH[3]);
                mma16816(o[2 * dp],     al, VH[0], VH[1]);
                mma16816(o[2 * dp + 1], al, VH[2], VH[3]);
                mma16816(o[2 * dp],     ah, VL[0], VL[1]);
                mma16816(o[2 * dp + 1], ah, VL[2], VL[3]);
            }
        }

        cp_wait0();
        __syncthreads();
    }

    // normalize + write O as bf16 hi/lo to [B,N,H*d]
    {
        const float inv0 = 1.0f / lrow0;
        const float inv1 = 1.0f / lrow1;
        const int r0 = q0 + m0 + (lane >> 2);
        const int cb = 2 * (lane & 3);
        const size_t base0 = ((size_t)(b * N_ + r0)) * INNER_ + h * D_;
        const size_t base1 = ((size_t)(b * N_ + r0 + 8)) * INNER_ + h * D_;
        #pragma unroll
        for (int ni = 0; ni < 8; ni++) {
            int dd = ni * 8 + cb;
            {
                float v0 = o[ni][0] * inv0, v1 = o[ni][1] * inv0;
                __nv_bfloat162 hv = __floats2bfloat162_rn(v0, v1);
                float2 hf = __bfloat1622float2(hv);
                __nv_bfloat162 lv = __floats2bfloat162_rn(v0 - hf.x, v1 - hf.y);
                *(uint32_t*)&g_ohh[base0 + dd] = u32bf2(hv);
                *(uint32_t*)&g_ohl[base0 + dd] = u32bf2(lv);
            }
            {
                float v0 = o[ni][2] * inv1, v1 = o[ni][3] * inv1;
                __nv_bfloat162 hv = __floats2bfloat162_rn(v0, v1);
                float2 hf = __bfloat1622float2(hv);
                __nv_bfloat162 lv = __floats2bfloat162_rn(v0 - hf.x, v1 - hf.y);
                *(uint32_t*)&g_ohh[base1 + dd] = u32bf2(hv);
                *(uint32_t*)&g_ohl[base1 + dd] = u32bf2(lv);
            }
        }
    }
}

// ---------------------------------------------------------------------------
extern "C" void kernel_launch(void* const* d_in, const int* in_sizes, int n_in,
                              void* d_out, int out_size)
{
    const float* x     = (const float*)d_in[0];
    const float* pos   = (const float*)d_in[1];
    const float* w_qkv = (const float*)d_in[2];
    const float* w_out = (const float*)d_in[3];
    const float* b_out = (const float*)d_in[4];
    float* out = (float*)d_out;

    static bool attr_set = false;
    if (!attr_set) {
        cudaFuncSetAttribute(flash_mma_kernel,
                             cudaFuncAttributeMaxDynamicSharedMemorySize,
                             SMEM_BYTES);
        attr_set = true;
    }

    // resolve device-global addresses for conversion outputs
    void *p_xh, *p_xl, *p_wqh, *p_wql, *p_woh, *p_wol;
    cudaGetSymbolAddress(&p_xh, g_xh);
    cudaGetSymbolAddress(&p_xl, g_xl);
    cudaGetSymbolAddress(&p_wqh, g_wqh);
    cudaGetSymbolAddress(&p_wql, g_wql);
    cudaGetSymbolAddress(&p_woh, g_woh);
    cudaGetSymbolAddress(&p_wol, g_wol);

    conv_split_kernel<<<(M_ * C_ / 4 + 255) / 256, 256>>>(
        (const float4*)x, (uint2*)p_xh, (uint2*)p_xl, M_ * C_ / 4);
    conv_split_kernel<<<(C_ * QKVCOLS_ / 4 + 255) / 256, 256>>>(
        (const float4*)w_qkv, (uint2*)p_wqh, (uint2*)p_wql, C_ * QKVCOLS_ / 4);
    conv_split_kernel<<<(INNER_ * C_ / 4 + 255) / 256, 256>>>(
        (const float4*)w_out, (uint2*)p_woh, (uint2*)p_wol, INNER_ * C_ / 4);

    gemm_qkv_mma<<<dim3(QKVCOLS_ / 64, M_ / 128), 256>>>();

    prep_kernel<<<R_TOTAL / 4, 256>>>(pos);

    flash_mma_kernel<<<dim3(N_ / BR, B_ * H_), 256, SMEM_BYTES>>>();

    gemm_out_mma<<<dim3(C_ / 64, M_ / 128), 256>>>(b_out, out);
}

// round 6
// speedup vs baseline: 5.2403x; 1.3205x over previous
#include <cuda_runtime.h>
#include <cuda_bf16.h>
#include <cuda_fp16.h>
#include <cstdint>

// Problem constants
#define B_   2
#define N_   4096
#define C_   512
#define H_   8
#define D_   64
#define INNER_ (H_ * D_)          // 512
#define QKVCOLS_ (INNER_ * 3)     // 1536
#define M_ (B_ * N_)              // 8192
#define R_TOTAL (B_ * H_ * N_)    // 65536 rows of 64

// Scratch (device globals; no cudaMalloc allowed)
__device__ float g_q[B_ * H_ * N_ * D_];
__device__ float g_k[B_ * H_ * N_ * D_];
__device__ float g_v[B_ * H_ * N_ * D_];
// fp16 versions (post-RoPE, q pre-scaled). q keeps hi/lo; k,v hi only.
__device__ __half g_qh[R_TOTAL * D_], g_ql[R_TOTAL * D_];
__device__ __half g_kh[R_TOTAL * D_];
__device__ __half g_vh[R_TOTAL * D_];
// bf16 split inputs for GEMMs
__device__ __nv_bfloat16 g_xh[M_ * C_], g_xl[M_ * C_];
__device__ __nv_bfloat16 g_wqh[C_ * QKVCOLS_], g_wql[C_ * QKVCOLS_];
__device__ __nv_bfloat16 g_woh[INNER_ * C_], g_wol[INNER_ * C_];
// attention output, bf16 split, [B,N,H*d]
__device__ __nv_bfloat16 g_ohh[B_ * N_ * INNER_], g_ohl[B_ * N_ * INNER_];

#define SCALE_LOG2E (0.125f * 1.4426950408889634f)

// ---------------------------------------------------------------------------
// common helpers
// ---------------------------------------------------------------------------
__device__ __forceinline__ uint32_t u32bf2(__nv_bfloat162 v)
{
    return reinterpret_cast<uint32_t&>(v);
}
__device__ __forceinline__ uint32_t u32h2(__half2 v)
{
    return reinterpret_cast<uint32_t&>(v);
}
__device__ __forceinline__ uint32_t swz(uint32_t row, uint32_t colb)
{
    uint32_t b = (row << 7) + colb;
    return b ^ ((b >> 3) & 0x70);
}
__device__ __forceinline__ uint32_t swzA(uint32_t row, uint32_t colb)
{
    uint32_t b = (row << 6) + colb;
    return b ^ ((b >> 3) & 0x30);
}
__device__ __forceinline__ void cp16(uint32_t dst, const void* src)
{
    asm volatile("cp.async.cg.shared.global [%0], [%1], 16;"
                 :: "r"(dst), "l"(src));
}
__device__ __forceinline__ void cp_commit()
{
    asm volatile("cp.async.commit_group;");
}
__device__ __forceinline__ void cp_wait0()
{
    asm volatile("cp.async.wait_group 0;");
}
__device__ __forceinline__ void cp_wait1()
{
    asm volatile("cp.async.wait_group 1;");
}
__device__ __forceinline__ void ldsm4(uint32_t a[4], uint32_t addr)
{
    asm volatile("ldmatrix.sync.aligned.m8n8.x4.shared.b16 {%0,%1,%2,%3}, [%4];"
                 : "=r"(a[0]), "=r"(a[1]), "=r"(a[2]), "=r"(a[3]) : "r"(addr));
}
__device__ __forceinline__ void ldsm4t(uint32_t a[4], uint32_t addr)
{
    asm volatile("ldmatrix.sync.aligned.m8n8.x4.trans.shared.b16 {%0,%1,%2,%3}, [%4];"
                 : "=r"(a[0]), "=r"(a[1]), "=r"(a[2]), "=r"(a[3]) : "r"(addr));
}
// bf16 MMA (used by GEMMs)
__device__ __forceinline__ void mma16816(float c[4], const uint32_t a[4],
                                         uint32_t b0, uint32_t b1)
{
    asm volatile(
        "mma.sync.aligned.m16n8k16.row.col.f32.bf16.bf16.f32 "
        "{%0,%1,%2,%3}, {%4,%5,%6,%7}, {%8,%9}, {%0,%1,%2,%3};"
        : "+f"(c[0]), "+f"(c[1]), "+f"(c[2]), "+f"(c[3])
        : "r"(a[0]), "r"(a[1]), "r"(a[2]), "r"(a[3]), "r"(b0), "r"(b1));
}
// fp16 MMA (used by flash)
__device__ __forceinline__ void mma16816h(float c[4], const uint32_t a[4],
                                          uint32_t b0, uint32_t b1)
{
    asm volatile(
        "mma.sync.aligned.m16n8k16.row.col.f32.f16.f16.f32 "
        "{%0,%1,%2,%3}, {%4,%5,%6,%7}, {%8,%9}, {%0,%1,%2,%3};"
        : "+f"(c[0]), "+f"(c[1]), "+f"(c[2]), "+f"(c[3])
        : "r"(a[0]), "r"(a[1]), "r"(a[2]), "r"(a[3]), "r"(b0), "r"(b1));
}

// ---------------------------------------------------------------------------
// K0: fp32 -> bf16 hi/lo split conversion (GEMM inputs)
// ---------------------------------------------------------------------------
__global__ __launch_bounds__(256) void conv_split_kernel(
    const float4* __restrict__ src, uint2* __restrict__ hi,
    uint2* __restrict__ lo, int n4)
{
    int i = blockIdx.x * 256 + threadIdx.x;
    if (i >= n4) return;
    float4 f = src[i];
    __nv_bfloat162 h0 = __floats2bfloat162_rn(f.x, f.y);
    __nv_bfloat162 h1 = __floats2bfloat162_rn(f.z, f.w);
    float2 a = __bfloat1622float2(h0), b = __bfloat1622float2(h1);
    __nv_bfloat162 l0 = __floats2bfloat162_rn(f.x - a.x, f.y - a.y);
    __nv_bfloat162 l1 = __floats2bfloat162_rn(f.z - b.x, f.w - b.y);
    hi[i] = make_uint2(u32bf2(h0), u32bf2(h1));
    lo[i] = make_uint2(u32bf2(l0), u32bf2(l1));
}

// ---------------------------------------------------------------------------
// Tensor-core GEMM machinery: BM=128, BN=64, BK=32, 2-stage cp.async. (bf16)
// ---------------------------------------------------------------------------
#define GSA_H 0
#define GSA_L 8192
#define GSB_H 16384
#define GSB_L 20480
#define GSTAGE 24576
#define GNKT (C_ / 32)   // 16

__device__ __forceinline__ void gemm_stage(
    uint32_t sb, uint32_t stg,
    const __nv_bfloat16* __restrict__ ah, const __nv_bfloat16* __restrict__ al,
    const __nv_bfloat16* __restrict__ bh, const __nv_bfloat16* __restrict__ bl,
    int m0, int n0, int k0, int ldb, int tid)
{
    #pragma unroll
    for (int i = 0; i < 6; i++) {
        int c = tid + i * 256;
        if (c < 512) {
            int row = c >> 2, col16 = c & 3;
            cp16(sb + stg + GSA_H + swzA(row, col16 * 16),
                 ah + (size_t)(m0 + row) * C_ + k0 + col16 * 8);
        } else if (c < 1024) {
            int cc = c - 512;
            int row = cc >> 2, col16 = cc & 3;
            cp16(sb + stg + GSA_L + swzA(row, col16 * 16),
                 al + (size_t)(m0 + row) * C_ + k0 + col16 * 8);
        } else if (c < 1280) {
            int cc = c - 1024;
            int row = cc >> 3, col16 = cc & 7;
            cp16(sb + stg + GSB_H + swz(row, col16 * 16),
                 bh + (size_t)(k0 + row) * ldb + n0 + col16 * 8);
        } else {
            int cc = c - 1280;
            int row = cc >> 3, col16 = cc & 7;
            cp16(sb + stg + GSB_L + swz(row, col16 * 16),
                 bl + (size_t)(k0 + row) * ldb + n0 + col16 * 8);
        }
    }
}

__device__ __forceinline__ void gemm_compute(
    uint32_t sb, uint32_t stg, float c[2][4][4], int wm, int wn, int lane)
{
    const int rA = lane & 15;
    const int cadd = (lane & 16) ? 16 : 0;
    #pragma unroll
    for (int t = 0; t < 2; t++) {
        uint32_t AH[2][4], AL[2][4], BH[2][4], BL[2][4];
        #pragma unroll
        for (int mi = 0; mi < 2; mi++) {
            uint32_t off = swzA(wm * 32 + mi * 16 + rA, t * 32 + cadd);
            ldsm4(AH[mi], sb + stg + GSA_H + off);
            ldsm4(AL[mi], sb + stg + GSA_L + off);
        }
        #pragma unroll
        for (int j2 = 0; j2 < 2; j2++) {
            uint32_t off = swz(t * 16 + rA, wn * 64 + j2 * 32 + cadd);
            ldsm4t(BH[j2], sb + stg + GSB_H + off);
            ldsm4t(BL[j2], sb + stg + GSB_L + off);
        }
        #pragma unroll
        for (int mi = 0; mi < 2; mi++) {
            #pragma unroll
            for (int j2 = 0; j2 < 2; j2++) {
                mma16816(c[mi][2 * j2],     AH[mi], BH[j2][0], BH[j2][1]);
                mma16816(c[mi][2 * j2 + 1], AH[mi], BH[j2][2], BH[j2][3]);
                mma16816(c[mi][2 * j2],     AL[mi], BH[j2][0], BH[j2][1]);
                mma16816(c[mi][2 * j2 + 1], AL[mi], BH[j2][2], BH[j2][3]);
                mma16816(c[mi][2 * j2],     AH[mi], BL[j2][0], BL[j2][1]);
                mma16816(c[mi][2 * j2 + 1], AH[mi], BL[j2][2], BL[j2][3]);
            }
        }
    }
}

// K1: QKV GEMM (tensor). grid (24, 64).
__global__ __launch_bounds__(256) void gemm_qkv_mma()
{
    __shared__ char smem[2 * GSTAGE];
    const uint32_t sb = (uint32_t)__cvta_generic_to_shared(smem);
    const int tid = threadIdx.x;
    const int wid = tid >> 5, lane = tid & 31;
    const int wm = wid >> 1, wn = wid & 1;
    const int m0 = blockIdx.y * 128;
    const int n0 = blockIdx.x * 64;

    float c[2][4][4] = {};

    gemm_stage(sb, 0,      g_xh, g_xl, g_wqh, g_wql, m0, n0, 0,  QKVCOLS_, tid);
    cp_commit();
    gemm_stage(sb, GSTAGE, g_xh, g_xl, g_wqh, g_wql, m0, n0, 32, QKVCOLS_, tid);
    cp_commit();

    for (int kt = 0; kt < GNKT; kt++) {
        if (kt < GNKT - 1) cp_wait1(); else cp_wait0();
        __syncthreads();
        gemm_compute(sb, (kt & 1) * GSTAGE, c, wm, wn, lane);
        __syncthreads();
        if (kt + 2 < GNKT) {
            gemm_stage(sb, (kt & 1) * GSTAGE, g_xh, g_xl, g_wqh, g_wql,
                       m0, n0, (kt + 2) * 32, QKVCOLS_, tid);
            cp_commit();
        }
    }

    const int part = n0 >> 9;
    const int h = (n0 & 511) >> 6;
    float* dst = (part == 0) ? g_q : (part == 1) ? g_k : g_v;
    #pragma unroll
    for (int mi = 0; mi < 2; mi++) {
        #pragma unroll
        for (int r8 = 0; r8 < 2; r8++) {
            const int mrow = m0 + wm * 32 + mi * 16 + r8 * 8 + (lane >> 2);
            const int b = mrow >> 12;
            const int n = mrow & (N_ - 1);
            const size_t base = ((size_t)(b * H_ + h) * N_ + n) * D_;
            #pragma unroll
            for (int nj = 0; nj < 4; nj++) {
                const int dd = wn * 32 + nj * 8 + (lane & 3) * 2;
                *(float2*)&dst[base + dd] =
                    make_float2(c[mi][nj][2 * r8], c[mi][nj][2 * r8 + 1]);
            }
        }
    }
}

// K4: output GEMM (tensor). grid (8, 64).
__global__ __launch_bounds__(256) void gemm_out_mma(
    const float* __restrict__ bias, float* __restrict__ out)
{
    __shared__ char smem[2 * GSTAGE];
    const uint32_t sb = (uint32_t)__cvta_generic_to_shared(smem);
    const int tid = threadIdx.x;
    const int wid = tid >> 5, lane = tid & 31;
    const int wm = wid >> 1, wn = wid & 1;
    const int m0 = blockIdx.y * 128;
    const int n0 = blockIdx.x * 64;

    float c[2][4][4] = {};

    gemm_stage(sb, 0,      g_ohh, g_ohl, g_woh, g_wol, m0, n0, 0,  C_, tid);
    cp_commit();
    gemm_stage(sb, GSTAGE, g_ohh, g_ohl, g_woh, g_wol, m0, n0, 32, C_, tid);
    cp_commit();

    for (int kt = 0; kt < GNKT; kt++) {
        if (kt < GNKT - 1) cp_wait1(); else cp_wait0();
        __syncthreads();
        gemm_compute(sb, (kt & 1) * GSTAGE, c, wm, wn, lane);
        __syncthreads();
        if (kt + 2 < GNKT) {
            gemm_stage(sb, (kt & 1) * GSTAGE, g_ohh, g_ohl, g_woh, g_wol,
                       m0, n0, (kt + 2) * 32, C_, tid);
            cp_commit();
        }
    }

    #pragma unroll
    for (int mi = 0; mi < 2; mi++) {
        #pragma unroll
        for (int r8 = 0; r8 < 2; r8++) {
            const int mrow = m0 + wm * 32 + mi * 16 + r8 * 8 + (lane >> 2);
            #pragma unroll
            for (int nj = 0; nj < 4; nj++) {
                const int col = n0 + wn * 32 + nj * 8 + (lane & 3) * 2;
                *(float2*)&out[(size_t)mrow * C_ + col] =
                    make_float2(c[mi][nj][2 * r8] + bias[col],
                                c[mi][nj][2 * r8 + 1] + bias[col + 1]);
            }
        }
    }
}

// ---------------------------------------------------------------------------
// K2: prep — RoPE(q,k) + scale q + fp16 conversion (q hi/lo; k,v hi only).
// ---------------------------------------------------------------------------
__global__ __launch_bounds__(256) void prep_kernel(const float* __restrict__ pos)
{
    const int tid = threadIdx.x;
    const int row = blockIdx.x * 4 + (tid >> 6);
    const int dd = tid & 63;
    const int n = row & (N_ - 1);
    const size_t idx = (size_t)row * D_ + dd;

    float sn, cs;
    __sincosf(pos[n * D_ + dd], &sn, &cs);
    const int partner = dd ^ 32;
    const float sign = (dd < 32) ? -1.0f : 1.0f;

    {
        const float t = g_q[idx];
        const float tp = g_q[(size_t)row * D_ + partner];
        const float r = (t * cs + sign * tp * sn) * SCALE_LOG2E;
        __half h = __float2half_rn(r);
        g_qh[idx] = h;
        g_ql[idx] = __float2half_rn(r - __half2float(h));
    }
    {
        const float t = g_k[idx];
        const float tp = g_k[(size_t)row * D_ + partner];
        g_kh[idx] = __float2half_rn(t * cs + sign * tp * sn);
    }
    g_vh[idx] = __float2half_rn(g_v[idx]);
}

// ---------------------------------------------------------------------------
// K3: flash attention (fp16). Q as (qh+ql) fp16 pair; K,V single fp16.
// QK: 2 MMAs/step. PV: 2 MMAs/step.
// ---------------------------------------------------------------------------
#define BR 128
#define BC 32
#define NT (N_ / BC)

#define SQ_H  0
#define SQ_L  16384
#define SKV   32768        // + stage*8192 ; K at +0, V at +4096
#define SMEM_BYTES 49152

__global__ __launch_bounds__(256, 2) void flash_mma_kernel()
{
    extern __shared__ char smraw[];
    const uint32_t sb = (uint32_t)__cvta_generic_to_shared(smraw);

    const int tid = threadIdx.x;
    const int wid = tid >> 5;
    const int lane = tid & 31;
    const int bh = blockIdx.y;
    const int b = bh >> 3, h = bh & 7;
    const int q0 = blockIdx.x * BR;

    // ---- stage Q hi/lo ----
    {
        const size_t qbase = ((size_t)bh * N_ + q0) * D_;
        #pragma unroll
        for (int i = 0; i < 8; i++) {
            int c = tid + i * 256;
            int arr = c >> 10;
            int cc = c & 1023;
            int row = cc >> 3;
            int col16 = cc & 7;
            const __half* src =
                (arr ? g_ql : g_qh) + qbase + (size_t)row * D_ + col16 * 8;
            cp16(sb + (arr ? SQ_L : SQ_H) + swz(row, col16 * 16), src);
        }
    }
    // ---- stage KV tile 0 ----
    {
        const size_t kvbase = (size_t)bh * N_ * D_;
        #pragma unroll
        for (int i = 0; i < 2; i++) {
            int c = tid + i * 256;            // 0..511
            int arr = c >> 8;                 // 0=K, 1=V
            int cc = c & 255;
            int row = cc >> 3;
            int col16 = cc & 7;
            cp16(sb + SKV + (arr ? 4096 : 0) + swz(row, col16 * 16),
                 (arr ? g_vh : g_kh) + kvbase + (size_t)row * D_ + col16 * 8);
        }
    }
    cp_commit();
    cp_wait0();
    __syncthreads();

    // ---- Q fragments (registers, whole kernel) ----
    const int m0 = wid * 16;
    uint32_t qh[4][4], ql[4][4];
    {
        int r = m0 + (lane & 15);
        int cadd = (lane & 16) ? 16 : 0;
        #pragma unroll
        for (int t = 0; t < 4; t++) {
            ldsm4(qh[t], sb + SQ_H + swz(r, t * 32 + cadd));
            ldsm4(ql[t], sb + SQ_L + swz(r, t * 32 + cadd));
        }
    }

    float o[8][4] = {};
    float mrow0 = -1e30f, mrow1 = -1e30f;
    float lrow0 = 0.f, lrow1 = 0.f;

    const size_t kvstride = (size_t)bh * N_ * D_;

    for (int kt = 0; kt < NT; kt++) {
        const uint32_t buf = (kt & 1) ? 8192 : 0;
        const uint32_t nbuf = (kt & 1) ? 0 : 8192;

        if (kt + 1 < NT) {
            const size_t kvbase = kvstride + (size_t)(kt + 1) * BC * D_;
            #pragma unroll
            for (int i = 0; i < 2; i++) {
                int c = tid + i * 256;
                int arr = c >> 8;
                int cc = c & 255;
                int row = cc >> 3;
                int col16 = cc & 7;
                cp16(sb + SKV + nbuf + (arr ? 4096 : 0) + swz(row, col16 * 16),
                     (arr ? g_vh : g_kh) + kvbase + (size_t)row * D_ + col16 * 8);
            }
            cp_commit();
        }

        // ---- S = Q K^T : (qh+ql)·k ----
        float s[4][4] = {};
        {
            const int rbase = lane & 15;
            const int cadd = (lane & 16) ? 16 : 0;
            #pragma unroll
            for (int p = 0; p < 2; p++) {
                #pragma unroll
                for (int t = 0; t < 4; t++) {
                    uint32_t KH[4];
                    ldsm4(KH, sb + SKV + buf + swz(p * 16 + rbase, t * 32 + cadd));
                    mma16816h(s[2 * p],     qh[t], KH[0], KH[2]);
                    mma16816h(s[2 * p + 1], qh[t], KH[1], KH[3]);
                    mma16816h(s[2 * p],     ql[t], KH[0], KH[2]);
                    mma16816h(s[2 * p + 1], ql[t], KH[1], KH[3]);
                }
            }
        }

        // ---- online softmax (base-2) ----
        float rmax0 = -1e30f, rmax1 = -1e30f;
        #pragma unroll
        for (int ni = 0; ni < 4; ni++) {
            rmax0 = fmaxf(rmax0, fmaxf(s[ni][0], s[ni][1]));
            rmax1 = fmaxf(rmax1, fmaxf(s[ni][2], s[ni][3]));
        }
        rmax0 = fmaxf(rmax0, __shfl_xor_sync(0xffffffffu, rmax0, 1));
        rmax0 = fmaxf(rmax0, __shfl_xor_sync(0xffffffffu, rmax0, 2));
        rmax1 = fmaxf(rmax1, __shfl_xor_sync(0xffffffffu, rmax1, 1));
        rmax1 = fmaxf(rmax1, __shfl_xor_sync(0xffffffffu, rmax1, 2));

        const float mn0 = fmaxf(mrow0, rmax0);
        const float mn1 = fmaxf(mrow1, rmax1);
        const float a0 = exp2f(mrow0 - mn0);
        const float a1 = exp2f(mrow1 - mn1);
        mrow0 = mn0; mrow1 = mn1;

        float sum0 = 0.f, sum1 = 0.f;
        #pragma unroll
        for (int ni = 0; ni < 4; ni++) {
            s[ni][0] = exp2f(s[ni][0] - mn0);
            s[ni][1] = exp2f(s[ni][1] - mn0);
            s[ni][2] = exp2f(s[ni][2] - mn1);
            s[ni][3] = exp2f(s[ni][3] - mn1);
            sum0 += s[ni][0] + s[ni][1];
            sum1 += s[ni][2] + s[ni][3];
        }
        sum0 += __shfl_xor_sync(0xffffffffu, sum0, 1);
        sum0 += __shfl_xor_sync(0xffffffffu, sum0, 2);
        sum1 += __shfl_xor_sync(0xffffffffu, sum1, 1);
        sum1 += __shfl_xor_sync(0xffffffffu, sum1, 2);
        lrow0 = lrow0 * a0 + sum0;
        lrow1 = lrow1 * a1 + sum1;

        #pragma unroll
        for (int ni = 0; ni < 8; ni++) {
            o[ni][0] *= a0; o[ni][1] *= a0;
            o[ni][2] *= a1; o[ni][3] *= a1;
        }

        // ---- O += P V : (ph+pl)·v ----
        #pragma unroll
        for (int t = 0; t < 2; t++) {
            uint32_t ah[4], al[4];
            {
                const float* p0 = s[2 * t];
                const float* p1 = s[2 * t + 1];
                __half2 hv; float2 hf;
                hv = __floats2half2_rn(p0[0], p0[1]); hf = __half22float2(hv);
                ah[0] = u32h2(hv);
                al[0] = u32h2(__floats2half2_rn(p0[0] - hf.x, p0[1] - hf.y));
                hv = __floats2half2_rn(p0[2], p0[3]); hf = __half22float2(hv);
                ah[1] = u32h2(hv);
                al[1] = u32h2(__floats2half2_rn(p0[2] - hf.x, p0[3] - hf.y));
                hv = __floats2half2_rn(p1[0], p1[1]); hf = __half22float2(hv);
                ah[2] = u32h2(hv);
                al[2] = u32h2(__floats2half2_rn(p1[0] - hf.x, p1[1] - hf.y));
                hv = __floats2half2_rn(p1[2], p1[3]); hf = __half22float2(hv);
                ah[3] = u32h2(hv);
                al[3] = u32h2(__floats2half2_rn(p1[2] - hf.x, p1[3] - hf.y));
            }
            const int rr = t * 16 + (lane & 15);
            const int cadd = (lane & 16) ? 16 : 0;
            #pragma unroll
            for (int dp = 0; dp < 4; dp++) {
                uint32_t VH[4];
                ldsm4t(VH, sb + SKV + buf + 4096 + swz(rr, dp * 32 + cadd));
                mma16816h(o[2 * dp],     ah, VH[0], VH[1]);
                mma16816h(o[2 * dp + 1], ah, VH[2], VH[3]);
                mma16816h(o[2 * dp],     al, VH[0], VH[1]);
                mma16816h(o[2 * dp + 1], al, VH[2], VH[3]);
            }
        }

        cp_wait0();
        __syncthreads();
    }

    // ---- normalize + write O as bf16 hi/lo to [B,N,H*d] ----
    {
        const float inv0 = 1.0f / lrow0;
        const float inv1 = 1.0f / lrow1;
        const int r0 = q0 + m0 + (lane >> 2);
        const int cb = 2 * (lane & 3);
        const size_t base0 = ((size_t)(b * N_ + r0)) * INNER_ + h * D_;
        const size_t base1 = ((size_t)(b * N_ + r0 + 8)) * INNER_ + h * D_;
        #pragma unroll
        for (int ni = 0; ni < 8; ni++) {
            int dd = ni * 8 + cb;
            {
                float v0 = o[ni][0] * inv0, v1 = o[ni][1] * inv0;
                __nv_bfloat162 hv = __floats2bfloat162_rn(v0, v1);
                float2 hf = __bfloat1622float2(hv);
                __nv_bfloat162 lv = __floats2bfloat162_rn(v0 - hf.x, v1 - hf.y);
                *(uint32_t*)&g_ohh[base0 + dd] = u32bf2(hv);
                *(uint32_t*)&g_ohl[base0 + dd] = u32bf2(lv);
            }
            {
                float v0 = o[ni][2] * inv1, v1 = o[ni][3] * inv1;
                __nv_bfloat162 hv = __floats2bfloat162_rn(v0, v1);
                float2 hf = __bfloat1622float2(hv);
                __nv_bfloat162 lv = __floats2bfloat162_rn(v0 - hf.x, v1 - hf.y);
                *(uint32_t*)&g_ohh[base1 + dd] = u32bf2(hv);
                *(uint32_t*)&g_ohl[base1 + dd] = u32bf2(lv);
            }
        }
    }
}

// ---------------------------------------------------------------------------
extern "C" void kernel_launch(void* const* d_in, const int* in_sizes, int n_in,
                              void* d_out, int out_size)
{
    const float* x     = (const float*)d_in[0];
    const float* pos   = (const float*)d_in[1];
    const float* w_qkv = (const float*)d_in[2];
    const float* w_out = (const float*)d_in[3];
    const float* b_out = (const float*)d_in[4];
    float* out = (float*)d_out;

    static bool attr_set = false;
    if (!attr_set) {
        cudaFuncSetAttribute(flash_mma_kernel,
                             cudaFuncAttributeMaxDynamicSharedMemorySize,
                             SMEM_BYTES);
        attr_set = true;
    }

    void *p_xh, *p_xl, *p_wqh, *p_wql, *p_woh, *p_wol;
    cudaGetSymbolAddress(&p_xh, g_xh);
    cudaGetSymbolAddress(&p_xl, g_xl);
    cudaGetSymbolAddress(&p_wqh, g_wqh);
    cudaGetSymbolAddress(&p_wql, g_wql);
    cudaGetSymbolAddress(&p_woh, g_woh);
    cudaGetSymbolAddress(&p_wol, g_wol);

    conv_split_kernel<<<(M_ * C_ / 4 + 255) / 256, 256>>>(
        (const float4*)x, (uint2*)p_xh, (uint2*)p_xl, M_ * C_ / 4);
    conv_split_kernel<<<(C_ * QKVCOLS_ / 4 + 255) / 256, 256>>>(
        (const float4*)w_qkv, (uint2*)p_wqh, (uint2*)p_wql, C_ * QKVCOLS_ / 4);
    conv_split_kernel<<<(INNER_ * C_ / 4 + 255) / 256, 256>>>(
        (const float4*)w_out, (uint2*)p_woh, (uint2*)p_wol, INNER_ * C_ / 4);

    gemm_qkv_mma<<<dim3(QKVCOLS_ / 64, M_ / 128), 256>>>();

    prep_kernel<<<R_TOTAL / 4, 256>>>(pos);

    flash_mma_kernel<<<dim3(N_ / BR, B_ * H_), 256, SMEM_BYTES>>>();

    gemm_out_mma<<<dim3(C_ / 64, M_ / 128), 256>>>(b_out, out);
}

// round 7
// speedup vs baseline: 7.5351x; 1.4379x over previous
#include <cuda_runtime.h>
#include <cuda_bf16.h>
#include <cuda_fp16.h>
#include <cstdint>

// Problem constants
#define B_   2
#define N_   4096
#define C_   512
#define H_   8
#define D_   64
#define INNER_ (H_ * D_)          // 512
#define QKVCOLS_ (INNER_ * 3)     // 1536
#define M_ (B_ * N_)              // 8192
#define R_TOTAL (B_ * H_ * N_)    // 65536 rows of 64

// Scratch (device globals; no cudaMalloc allowed)
__device__ float g_q[B_ * H_ * N_ * D_];
__device__ float g_k[B_ * H_ * N_ * D_];
__device__ float g_v[B_ * H_ * N_ * D_];
// fp16 attention inputs (post-RoPE, q pre-scaled); single precision each
__device__ __half g_qh[R_TOTAL * D_];
__device__ __half g_kh[R_TOTAL * D_];
__device__ __half g_vh[R_TOTAL * D_];
// fp16 GEMM inputs: activations hi/lo, weights single
__device__ __half g_xh[M_ * C_], g_xl[M_ * C_];
__device__ __half g_wq[C_ * QKVCOLS_];
__device__ __half g_wo[INNER_ * C_];
// attention output, fp16 hi/lo, [B,N,H*d]
__device__ __half g_ohh[B_ * N_ * INNER_], g_ohl[B_ * N_ * INNER_];

#define SCALE_LOG2E (0.125f * 1.4426950408889634f)

// ---------------------------------------------------------------------------
// common helpers
// ---------------------------------------------------------------------------
__device__ __forceinline__ uint32_t u32h2(__half2 v)
{
    return reinterpret_cast<uint32_t&>(v);
}
__device__ __forceinline__ uint32_t swz(uint32_t row, uint32_t colb)
{
    uint32_t b = (row << 7) + colb;     // 128B rows
    return b ^ ((b >> 3) & 0x70);
}
__device__ __forceinline__ uint32_t swzA(uint32_t row, uint32_t colb)
{
    uint32_t b = (row << 6) + colb;     // 64B rows
    return b ^ ((b >> 3) & 0x30);
}
__device__ __forceinline__ void cp16(uint32_t dst, const void* src)
{
    asm volatile("cp.async.cg.shared.global [%0], [%1], 16;"
                 :: "r"(dst), "l"(src));
}
__device__ __forceinline__ void cp_commit()
{
    asm volatile("cp.async.commit_group;");
}
__device__ __forceinline__ void cp_wait0()
{
    asm volatile("cp.async.wait_group 0;");
}
__device__ __forceinline__ void cp_wait1()
{
    asm volatile("cp.async.wait_group 1;");
}
__device__ __forceinline__ void ldsm4(uint32_t a[4], uint32_t addr)
{
    asm volatile("ldmatrix.sync.aligned.m8n8.x4.shared.b16 {%0,%1,%2,%3}, [%4];"
                 : "=r"(a[0]), "=r"(a[1]), "=r"(a[2]), "=r"(a[3]) : "r"(addr));
}
__device__ __forceinline__ void ldsm4t(uint32_t a[4], uint32_t addr)
{
    asm volatile("ldmatrix.sync.aligned.m8n8.x4.trans.shared.b16 {%0,%1,%2,%3}, [%4];"
                 : "=r"(a[0]), "=r"(a[1]), "=r"(a[2]), "=r"(a[3]) : "r"(addr));
}
__device__ __forceinline__ void mma16816h(float c[4], const uint32_t a[4],
                                          uint32_t b0, uint32_t b1)
{
    asm volatile(
        "mma.sync.aligned.m16n8k16.row.col.f32.f16.f16.f32 "
        "{%0,%1,%2,%3}, {%4,%5,%6,%7}, {%8,%9}, {%0,%1,%2,%3};"
        : "+f"(c[0]), "+f"(c[1]), "+f"(c[2]), "+f"(c[3])
        : "r"(a[0]), "r"(a[1]), "r"(a[2]), "r"(a[3]), "r"(b0), "r"(b1));
}

// ---------------------------------------------------------------------------
// K0a: fp32 -> fp16 hi/lo split (activations)
// ---------------------------------------------------------------------------
__global__ __launch_bounds__(256) void conv_split_h(
    const float4* __restrict__ src, uint2* __restrict__ hi,
    uint2* __restrict__ lo, int n4)
{
    int i = blockIdx.x * 256 + threadIdx.x;
    if (i >= n4) return;
    float4 f = src[i];
    __half2 h0 = __floats2half2_rn(f.x, f.y);
    __half2 h1 = __floats2half2_rn(f.z, f.w);
    float2 a = __half22float2(h0), b = __half22float2(h1);
    __half2 l0 = __floats2half2_rn(f.x - a.x, f.y - a.y);
    __half2 l1 = __floats2half2_rn(f.z - b.x, f.w - b.y);
    hi[i] = make_uint2(u32h2(h0), u32h2(h1));
    lo[i] = make_uint2(u32h2(l0), u32h2(l1));
}

// K0b: fp32 -> fp16 single (weights)
__global__ __launch_bounds__(256) void conv_single_h(
    const float4* __restrict__ src, uint2* __restrict__ dst, int n4)
{
    int i = blockIdx.x * 256 + threadIdx.x;
    if (i >= n4) return;
    float4 f = src[i];
    dst[i] = make_uint2(u32h2(__floats2half2_rn(f.x, f.y)),
                        u32h2(__floats2half2_rn(f.z, f.w)));
}

// ---------------------------------------------------------------------------
// Tensor-core GEMM: BM=128, BN=64, BK=32, 2-stage cp.async, fp16 2-term.
// A = activations (hi+lo), B = weights (single).
// ---------------------------------------------------------------------------
#define GSA_H 0
#define GSA_L 8192
#define GSB   16384
#define GSTAGE 20480
#define GNKT (C_ / 32)   // 16

__device__ __forceinline__ void gemm_stage(
    uint32_t sb, uint32_t stg,
    const __half* __restrict__ ah, const __half* __restrict__ al,
    const __half* __restrict__ bw,
    int m0, int n0, int k0, int ldb, int tid)
{
    #pragma unroll
    for (int i = 0; i < 5; i++) {
        int c = tid + i * 256;               // 0..1279
        if (c < 512) {
            int row = c >> 2, col16 = c & 3;
            cp16(sb + stg + GSA_H + swzA(row, col16 * 16),
                 ah + (size_t)(m0 + row) * C_ + k0 + col16 * 8);
        } else if (c < 1024) {
            int cc = c - 512;
            int row = cc >> 2, col16 = cc & 3;
            cp16(sb + stg + GSA_L + swzA(row, col16 * 16),
                 al + (size_t)(m0 + row) * C_ + k0 + col16 * 8);
        } else {
            int cc = c - 1024;               // 0..255
            int row = cc >> 3, col16 = cc & 7;
            cp16(sb + stg + GSB + swz(row, col16 * 16),
                 bw + (size_t)(k0 + row) * ldb + n0 + col16 * 8);
        }
    }
}

__device__ __forceinline__ void gemm_compute(
    uint32_t sb, uint32_t stg, float c[2][4][4], int wm, int wn, int lane)
{
    const int rA = lane & 15;
    const int cadd = (lane & 16) ? 16 : 0;
    #pragma unroll
    for (int t = 0; t < 2; t++) {
        uint32_t AH[2][4], AL[2][4], BW[2][4];
        #pragma unroll
        for (int mi = 0; mi < 2; mi++) {
            uint32_t off = swzA(wm * 32 + mi * 16 + rA, t * 32 + cadd);
            ldsm4(AH[mi], sb + stg + GSA_H + off);
            ldsm4(AL[mi], sb + stg + GSA_L + off);
        }
        #pragma unroll
        for (int j2 = 0; j2 < 2; j2++) {
            uint32_t off = swz(t * 16 + rA, wn * 64 + j2 * 32 + cadd);
            ldsm4t(BW[j2], sb + stg + GSB + off);
        }
        #pragma unroll
        for (int mi = 0; mi < 2; mi++) {
            #pragma unroll
            for (int j2 = 0; j2 < 2; j2++) {
                mma16816h(c[mi][2 * j2],     AH[mi], BW[j2][0], BW[j2][1]);
                mma16816h(c[mi][2 * j2 + 1], AH[mi], BW[j2][2], BW[j2][3]);
                mma16816h(c[mi][2 * j2],     AL[mi], BW[j2][0], BW[j2][1]);
                mma16816h(c[mi][2 * j2 + 1], AL[mi], BW[j2][2], BW[j2][3]);
            }
        }
    }
}

// K1: QKV GEMM (tensor). grid (24, 64).
__global__ __launch_bounds__(256) void gemm_qkv_mma()
{
    __shared__ char smem[2 * GSTAGE];
    const uint32_t sb = (uint32_t)__cvta_generic_to_shared(smem);
    const int tid = threadIdx.x;
    const int wid = tid >> 5, lane = tid & 31;
    const int wm = wid >> 1, wn = wid & 1;
    const int m0 = blockIdx.y * 128;
    const int n0 = blockIdx.x * 64;

    float c[2][4][4] = {};

    gemm_stage(sb, 0,      g_xh, g_xl, g_wq, m0, n0, 0,  QKVCOLS_, tid);
    cp_commit();
    gemm_stage(sb, GSTAGE, g_xh, g_xl, g_wq, m0, n0, 32, QKVCOLS_, tid);
    cp_commit();

    for (int kt = 0; kt < GNKT; kt++) {
        if (kt < GNKT - 1) cp_wait1(); else cp_wait0();
        __syncthreads();
        gemm_compute(sb, (kt & 1) * GSTAGE, c, wm, wn, lane);
        __syncthreads();
        if (kt + 2 < GNKT) {
            gemm_stage(sb, (kt & 1) * GSTAGE, g_xh, g_xl, g_wq,
                       m0, n0, (kt + 2) * 32, QKVCOLS_, tid);
            cp_commit();
        }
    }

    const int part = n0 >> 9;
    const int h = (n0 & 511) >> 6;
    float* dst = (part == 0) ? g_q : (part == 1) ? g_k : g_v;
    #pragma unroll
    for (int mi = 0; mi < 2; mi++) {
        #pragma unroll
        for (int r8 = 0; r8 < 2; r8++) {
            const int mrow = m0 + wm * 32 + mi * 16 + r8 * 8 + (lane >> 2);
            const int b = mrow >> 12;
            const int n = mrow & (N_ - 1);
            const size_t base = ((size_t)(b * H_ + h) * N_ + n) * D_;
            #pragma unroll
            for (int nj = 0; nj < 4; nj++) {
                const int dd = wn * 32 + nj * 8 + (lane & 3) * 2;
                *(float2*)&dst[base + dd] =
                    make_float2(c[mi][nj][2 * r8], c[mi][nj][2 * r8 + 1]);
            }
        }
    }
}

// K4: output GEMM (tensor). grid (8, 64).
__global__ __launch_bounds__(256) void gemm_out_mma(
    const float* __restrict__ bias, float* __restrict__ out)
{
    __shared__ char smem[2 * GSTAGE];
    const uint32_t sb = (uint32_t)__cvta_generic_to_shared(smem);
    const int tid = threadIdx.x;
    const int wid = tid >> 5, lane = tid & 31;
    const int wm = wid >> 1, wn = wid & 1;
    const int m0 = blockIdx.y * 128;
    const int n0 = blockIdx.x * 64;

    float c[2][4][4] = {};

    gemm_stage(sb, 0,      g_ohh, g_ohl, g_wo, m0, n0, 0,  C_, tid);
    cp_commit();
    gemm_stage(sb, GSTAGE, g_ohh, g_ohl, g_wo, m0, n0, 32, C_, tid);
    cp_commit();

    for (int kt = 0; kt < GNKT; kt++) {
        if (kt < GNKT - 1) cp_wait1(); else cp_wait0();
        __syncthreads();
        gemm_compute(sb, (kt & 1) * GSTAGE, c, wm, wn, lane);
        __syncthreads();
        if (kt + 2 < GNKT) {
            gemm_stage(sb, (kt & 1) * GSTAGE, g_ohh, g_ohl, g_wo,
                       m0, n0, (kt + 2) * 32, C_, tid);
            cp_commit();
        }
    }

    #pragma unroll
    for (int mi = 0; mi < 2; mi++) {
        #pragma unroll
        for (int r8 = 0; r8 < 2; r8++) {
            const int mrow = m0 + wm * 32 + mi * 16 + r8 * 8 + (lane >> 2);
            #pragma unroll
            for (int nj = 0; nj < 4; nj++) {
                const int col = n0 + wn * 32 + nj * 8 + (lane & 3) * 2;
                *(float2*)&out[(size_t)mrow * C_ + col] =
                    make_float2(c[mi][nj][2 * r8] + bias[col],
                                c[mi][nj][2 * r8 + 1] + bias[col + 1]);
            }
        }
    }
}

// ---------------------------------------------------------------------------
// K2: prep — RoPE(q,k) + scale q + fp16 conversion (single precision).
// ---------------------------------------------------------------------------
__global__ __launch_bounds__(256) void prep_kernel(const float* __restrict__ pos)
{
    const int tid = threadIdx.x;
    const int row = blockIdx.x * 4 + (tid >> 6);
    const int dd = tid & 63;
    const int n = row & (N_ - 1);
    const size_t idx = (size_t)row * D_ + dd;

    float sn, cs;
    __sincosf(pos[n * D_ + dd], &sn, &cs);
    const int partner = dd ^ 32;
    const float sign = (dd < 32) ? -1.0f : 1.0f;

    {
        const float t = g_q[idx];
        const float tp = g_q[(size_t)row * D_ + partner];
        g_qh[idx] = __float2half_rn((t * cs + sign * tp * sn) * SCALE_LOG2E);
    }
    {
        const float t = g_k[idx];
        const float tp = g_k[(size_t)row * D_ + partner];
        g_kh[idx] = __float2half_rn(t * cs + sign * tp * sn);
    }
    g_vh[idx] = __float2half_rn(g_v[idx]);
}

// ---------------------------------------------------------------------------
// K3: flash attention, pure fp16 mma.sync, cp.async double-buffered K/V.
// QK: 1-term (q·k). PV: 1-term (p·v). fp32 accumulate throughout.
// ---------------------------------------------------------------------------
#define BR 128
#define BC 32
#define NT (N_ / BC)

#define SQ    0
#define SKV   16384        // + stage*8192 ; K at +0, V at +4096
#define SMEM_BYTES 32768

__global__ __launch_bounds__(256, 2) void flash_mma_kernel()
{
    extern __shared__ char smraw[];
    const uint32_t sb = (uint32_t)__cvta_generic_to_shared(smraw);

    const int tid = threadIdx.x;
    const int wid = tid >> 5;
    const int lane = tid & 31;
    const int bh = blockIdx.y;
    const int b = bh >> 3, h = bh & 7;
    const int q0 = blockIdx.x * BR;

    // ---- stage Q ----
    {
        const size_t qbase = ((size_t)bh * N_ + q0) * D_;
        #pragma unroll
        for (int i = 0; i < 4; i++) {
            int c = tid + i * 256;            // 0..1023
            int row = c >> 3;
            int col16 = c & 7;
            cp16(sb + SQ + swz(row, col16 * 16),
                 g_qh + qbase + (size_t)row * D_ + col16 * 8);
        }
    }
    // ---- stage KV tile 0 ----
    {
        const size_t kvbase = (size_t)bh * N_ * D_;
        #pragma unroll
        for (int i = 0; i < 2; i++) {
            int c = tid + i * 256;            // 0..511
            int arr = c >> 8;                 // 0=K, 1=V
            int cc = c & 255;
            int row = cc >> 3;
            int col16 = cc & 7;
            cp16(sb + SKV + (arr ? 4096 : 0) + swz(row, col16 * 16),
                 (arr ? g_vh : g_kh) + kvbase + (size_t)row * D_ + col16 * 8);
        }
    }
    cp_commit();
    cp_wait0();
    __syncthreads();

    // ---- Q fragments (registers, whole kernel) ----
    const int m0 = wid * 16;
    uint32_t qh[4][4];
    {
        int r = m0 + (lane & 15);
        int cadd = (lane & 16) ? 16 : 0;
        #pragma unroll
        for (int t = 0; t < 4; t++)
            ldsm4(qh[t], sb + SQ + swz(r, t * 32 + cadd));
    }

    float o[8][4] = {};
    float mrow0 = -1e30f, mrow1 = -1e30f;
    float lrow0 = 0.f, lrow1 = 0.f;

    const size_t kvstride = (size_t)bh * N_ * D_;

    for (int kt = 0; kt < NT; kt++) {
        const uint32_t buf = (kt & 1) ? 8192 : 0;
        const uint32_t nbuf = (kt & 1) ? 0 : 8192;

        if (kt + 1 < NT) {
            const size_t kvbase = kvstride + (size_t)(kt + 1) * BC * D_;
            #pragma unroll
            for (int i = 0; i < 2; i++) {
                int c = tid + i * 256;
                int arr = c >> 8;
                int cc = c & 255;
                int row = cc >> 3;
                int col16 = cc & 7;
                cp16(sb + SKV + nbuf + (arr ? 4096 : 0) + swz(row, col16 * 16),
                     (arr ? g_vh : g_kh) + kvbase + (size_t)row * D_ + col16 * 8);
            }
            cp_commit();
        }

        // ---- S = Q K^T ----
        float s[4][4] = {};
        {
            const int rbase = lane & 15;
            const int cadd = (lane & 16) ? 16 : 0;
            #pragma unroll
            for (int p = 0; p < 2; p++) {
                #pragma unroll
                for (int t = 0; t < 4; t++) {
                    uint32_t KH[4];
                    ldsm4(KH, sb + SKV + buf + swz(p * 16 + rbase, t * 32 + cadd));
                    mma16816h(s[2 * p],     qh[t], KH[0], KH[2]);
                    mma16816h(s[2 * p + 1], qh[t], KH[1], KH[3]);
                }
            }
        }

        // ---- online softmax (base-2) ----
        float rmax0 = -1e30f, rmax1 = -1e30f;
        #pragma unroll
        for (int ni = 0; ni < 4; ni++) {
            rmax0 = fmaxf(rmax0, fmaxf(s[ni][0], s[ni][1]));
            rmax1 = fmaxf(rmax1, fmaxf(s[ni][2], s[ni][3]));
        }
        rmax0 = fmaxf(rmax0, __shfl_xor_sync(0xffffffffu, rmax0, 1));
        rmax0 = fmaxf(rmax0, __shfl_xor_sync(0xffffffffu, rmax0, 2));
        rmax1 = fmaxf(rmax1, __shfl_xor_sync(0xffffffffu, rmax1, 1));
        rmax1 = fmaxf(rmax1, __shfl_xor_sync(0xffffffffu, rmax1, 2));

        const float mn0 = fmaxf(mrow0, rmax0);
        const float mn1 = fmaxf(mrow1, rmax1);
        const float a0 = exp2f(mrow0 - mn0);
        const float a1 = exp2f(mrow1 - mn1);
        mrow0 = mn0; mrow1 = mn1;

        float sum0 = 0.f, sum1 = 0.f;
        #pragma unroll
        for (int ni = 0; ni < 4; ni++) {
            s[ni][0] = exp2f(s[ni][0] - mn0);
            s[ni][1] = exp2f(s[ni][1] - mn0);
            s[ni][2] = exp2f(s[ni][2] - mn1);
            s[ni][3] = exp2f(s[ni][3] - mn1);
            sum0 += s[ni][0] + s[ni][1];
            sum1 += s[ni][2] + s[ni][3];
        }
        sum0 += __shfl_xor_sync(0xffffffffu, sum0, 1);
        sum0 += __shfl_xor_sync(0xffffffffu, sum0, 2);
        sum1 += __shfl_xor_sync(0xffffffffu, sum1, 1);
        sum1 += __shfl_xor_sync(0xffffffffu, sum1, 2);
        lrow0 = lrow0 * a0 + sum0;
        lrow1 = lrow1 * a1 + sum1;

        #pragma unroll
        for (int ni = 0; ni < 8; ni++) {
            o[ni][0] *= a0; o[ni][1] *= a0;
            o[ni][2] *= a1; o[ni][3] *= a1;
        }

        // ---- O += P V ----
        #pragma unroll
        for (int t = 0; t < 2; t++) {
            uint32_t ah[4];
            {
                const float* p0 = s[2 * t];
                const float* p1 = s[2 * t + 1];
                ah[0] = u32h2(__floats2half2_rn(p0[0], p0[1]));
                ah[1] = u32h2(__floats2half2_rn(p0[2], p0[3]));
                ah[2] = u32h2(__floats2half2_rn(p1[0], p1[1]));
                ah[3] = u32h2(__floats2half2_rn(p1[2], p1[3]));
            }
            const int rr = t * 16 + (lane & 15);
            const int cadd = (lane & 16) ? 16 : 0;
            #pragma unroll
            for (int dp = 0; dp < 4; dp++) {
                uint32_t VH[4];
                ldsm4t(VH, sb + SKV + buf + 4096 + swz(rr, dp * 32 + cadd));
                mma16816h(o[2 * dp],     ah, VH[0], VH[1]);
                mma16816h(o[2 * dp + 1], ah, VH[2], VH[3]);
            }
        }

        cp_wait0();
        __syncthreads();
    }

    // ---- normalize + write O as fp16 hi/lo to [B,N,H*d] ----
    {
        const float inv0 = 1.0f / lrow0;
        const float inv1 = 1.0f / lrow1;
        const int r0 = q0 + m0 + (lane >> 2);
        const int cb = 2 * (lane & 3);
        const size_t base0 = ((size_t)(b * N_ + r0)) * INNER_ + h * D_;
        const size_t base1 = ((size_t)(b * N_ + r0 + 8)) * INNER_ + h * D_;
        #pragma unroll
        for (int ni = 0; ni < 8; ni++) {
            int dd = ni * 8 + cb;
            {
                float v0 = o[ni][0] * inv0, v1 = o[ni][1] * inv0;
                __half2 hv = __floats2half2_rn(v0, v1);
                float2 hf = __half22float2(hv);
                __half2 lv = __floats2half2_rn(v0 - hf.x, v1 - hf.y);
                *(uint32_t*)&g_ohh[base0 + dd] = u32h2(hv);
                *(uint32_t*)&g_ohl[base0 + dd] = u32h2(lv);
            }
            {
                float v0 = o[ni][2] * inv1, v1 = o[ni][3] * inv1;
                __half2 hv = __floats2half2_rn(v0, v1);
                float2 hf = __half22float2(hv);
                __half2 lv = __floats2half2_rn(v0 - hf.x, v1 - hf.y);
                *(uint32_t*)&g_ohh[base1 + dd] = u32h2(hv);
                *(uint32_t*)&g_ohl[base1 + dd] = u32h2(lv);
            }
        }
    }
}

// ---------------------------------------------------------------------------
extern "C" void kernel_launch(void* const* d_in, const int* in_sizes, int n_in,
                              void* d_out, int out_size)
{
    const float* x     = (const float*)d_in[0];
    const float* pos   = (const float*)d_in[1];
    const float* w_qkv = (const float*)d_in[2];
    const float* w_out = (const float*)d_in[3];
    const float* b_out = (const float*)d_in[4];
    float* out = (float*)d_out;

    static bool attr_set = false;
    if (!attr_set) {
        cudaFuncSetAttribute(flash_mma_kernel,
                             cudaFuncAttributeMaxDynamicSharedMemorySize,
                             SMEM_BYTES);
        attr_set = true;
    }

    void *p_xh, *p_xl, *p_wq, *p_wo;
    cudaGetSymbolAddress(&p_xh, g_xh);
    cudaGetSymbolAddress(&p_xl, g_xl);
    cudaGetSymbolAddress(&p_wq, g_wq);
    cudaGetSymbolAddress(&p_wo, g_wo);

    conv_split_h<<<(M_ * C_ / 4 + 255) / 256, 256>>>(
        (const float4*)x, (uint2*)p_xh, (uint2*)p_xl, M_ * C_ / 4);
    conv_single_h<<<(C_ * QKVCOLS_ / 4 + 255) / 256, 256>>>(
        (const float4*)w_qkv, (uint2*)p_wq, C_ * QKVCOLS_ / 4);
    conv_single_h<<<(INNER_ * C_ / 4 + 255) / 256, 256>>>(
        (const float4*)w_out, (uint2*)p_wo, INNER_ * C_ / 4);

    gemm_qkv_mma<<<dim3(QKVCOLS_ / 64, M_ / 128), 256>>>();

    prep_kernel<<<R_TOTAL / 4, 256>>>(pos);

    flash_mma_kernel<<<dim3(N_ / BR, B_ * H_), 256, SMEM_BYTES>>>();

    gemm_out_mma<<<dim3(C_ / 64, M_ / 128), 256>>>(b_out, out);
}

// round 8
// speedup vs baseline: 8.3620x; 1.1097x over previous
#include <cuda_runtime.h>
#include <cuda_bf16.h>
#include <cuda_fp16.h>
#include <cstdint>

// Problem constants
#define B_   2
#define N_   4096
#define C_   512
#define H_   8
#define D_   64
#define INNER_ (H_ * D_)          // 512
#define QKVCOLS_ (INNER_ * 3)     // 1536
#define M_ (B_ * N_)              // 8192
#define R_TOTAL (B_ * H_ * N_)    // 65536 rows of 64

// Scratch (device globals; no cudaMalloc allowed)
__device__ float g_q[B_ * H_ * N_ * D_];
__device__ float g_k[B_ * H_ * N_ * D_];
__device__ float g_v[B_ * H_ * N_ * D_];
// fp16 attention inputs (post-RoPE, q pre-scaled)
__device__ __half g_qh[R_TOTAL * D_];
__device__ __half g_kh[R_TOTAL * D_];
__device__ __half g_vh[R_TOTAL * D_];
// fp16 GEMM inputs: activations hi/lo, weights single
__device__ __half g_xh[M_ * C_], g_xl[M_ * C_];
__device__ __half g_wq[C_ * QKVCOLS_];
__device__ __half g_wo[INNER_ * C_];
// attention output, fp16 hi/lo, [B,N,H*d]
__device__ __half g_ohh[B_ * N_ * INNER_], g_ohl[B_ * N_ * INNER_];

#define SCALE_LOG2E (0.125f * 1.4426950408889634f)

// ---------------------------------------------------------------------------
// common helpers
// ---------------------------------------------------------------------------
__device__ __forceinline__ uint32_t u32h2(__half2 v)
{
    return reinterpret_cast<uint32_t&>(v);
}
__device__ __forceinline__ float ex2(float x)
{
    float y;
    asm("ex2.approx.ftz.f32 %0, %1;" : "=f"(y) : "f"(x));
    return y;
}
__device__ __forceinline__ uint32_t swz(uint32_t row, uint32_t colb)
{
    uint32_t b = (row << 7) + colb;     // 128B rows
    return b ^ ((b >> 3) & 0x70);
}
__device__ __forceinline__ uint32_t swzA(uint32_t row, uint32_t colb)
{
    uint32_t b = (row << 6) + colb;     // 64B rows
    return b ^ ((b >> 3) & 0x30);
}
__device__ __forceinline__ void cp16(uint32_t dst, const void* src)
{
    asm volatile("cp.async.cg.shared.global [%0], [%1], 16;"
                 :: "r"(dst), "l"(src));
}
__device__ __forceinline__ void cp_commit()
{
    asm volatile("cp.async.commit_group;");
}
__device__ __forceinline__ void cp_wait0()
{
    asm volatile("cp.async.wait_group 0;");
}
__device__ __forceinline__ void cp_wait1()
{
    asm volatile("cp.async.wait_group 1;");
}
__device__ __forceinline__ void ldsm4(uint32_t a[4], uint32_t addr)
{
    asm volatile("ldmatrix.sync.aligned.m8n8.x4.shared.b16 {%0,%1,%2,%3}, [%4];"
                 : "=r"(a[0]), "=r"(a[1]), "=r"(a[2]), "=r"(a[3]) : "r"(addr));
}
__device__ __forceinline__ void ldsm4t(uint32_t a[4], uint32_t addr)
{
    asm volatile("ldmatrix.sync.aligned.m8n8.x4.trans.shared.b16 {%0,%1,%2,%3}, [%4];"
                 : "=r"(a[0]), "=r"(a[1]), "=r"(a[2]), "=r"(a[3]) : "r"(addr));
}
__device__ __forceinline__ void mma16816h(float c[4], const uint32_t a[4],
                                          uint32_t b0, uint32_t b1)
{
    asm volatile(
        "mma.sync.aligned.m16n8k16.row.col.f32.f16.f16.f32 "
        "{%0,%1,%2,%3}, {%4,%5,%6,%7}, {%8,%9}, {%0,%1,%2,%3};"
        : "+f"(c[0]), "+f"(c[1]), "+f"(c[2]), "+f"(c[3])
        : "r"(a[0]), "r"(a[1]), "r"(a[2]), "r"(a[3]), "r"(b0), "r"(b1));
}

// ---------------------------------------------------------------------------
// K0a: fp32 -> fp16 hi/lo split (activations)
// ---------------------------------------------------------------------------
__global__ __launch_bounds__(256) void conv_split_h(
    const float4* __restrict__ src, uint2* __restrict__ hi,
    uint2* __restrict__ lo, int n4)
{
    int i = blockIdx.x * 256 + threadIdx.x;
    if (i >= n4) return;
    float4 f = src[i];
    __half2 h0 = __floats2half2_rn(f.x, f.y);
    __half2 h1 = __floats2half2_rn(f.z, f.w);
    float2 a = __half22float2(h0), b = __half22float2(h1);
    __half2 l0 = __floats2half2_rn(f.x - a.x, f.y - a.y);
    __half2 l1 = __floats2half2_rn(f.z - b.x, f.w - b.y);
    hi[i] = make_uint2(u32h2(h0), u32h2(h1));
    lo[i] = make_uint2(u32h2(l0), u32h2(l1));
}

// K0b: fp32 -> fp16 single (weights)
__global__ __launch_bounds__(256) void conv_single_h(
    const float4* __restrict__ src, uint2* __restrict__ dst, int n4)
{
    int i = blockIdx.x * 256 + threadIdx.x;
    if (i >= n4) return;
    float4 f = src[i];
    dst[i] = make_uint2(u32h2(__floats2half2_rn(f.x, f.y)),
                        u32h2(__floats2half2_rn(f.z, f.w)));
}

// ---------------------------------------------------------------------------
// Tensor-core GEMM: BM=128, BN=64, BK=32, 2-stage cp.async, fp16 2-term.
// ---------------------------------------------------------------------------
#define GSA_H 0
#define GSA_L 8192
#define GSB   16384
#define GSTAGE 20480
#define GNKT (C_ / 32)   // 16

__device__ __forceinline__ void gemm_stage(
    uint32_t sb, uint32_t stg,
    const __half* __restrict__ ah, const __half* __restrict__ al,
    const __half* __restrict__ bw,
    int m0, int n0, int k0, int ldb, int tid)
{
    #pragma unroll
    for (int i = 0; i < 5; i++) {
        int c = tid + i * 256;               // 0..1279
        if (c < 512) {
            int row = c >> 2, col16 = c & 3;
            cp16(sb + stg + GSA_H + swzA(row, col16 * 16),
                 ah + (size_t)(m0 + row) * C_ + k0 + col16 * 8);
        } else if (c < 1024) {
            int cc = c - 512;
            int row = cc >> 2, col16 = cc & 3;
            cp16(sb + stg + GSA_L + swzA(row, col16 * 16),
                 al + (size_t)(m0 + row) * C_ + k0 + col16 * 8);
        } else {
            int cc = c - 1024;               // 0..255
            int row = cc >> 3, col16 = cc & 7;
            cp16(sb + stg + GSB + swz(row, col16 * 16),
                 bw + (size_t)(k0 + row) * ldb + n0 + col16 * 8);
        }
    }
}

__device__ __forceinline__ void gemm_compute(
    uint32_t sb, uint32_t stg, float c[2][4][4], int wm, int wn, int lane)
{
    const int rA = lane & 15;
    const int cadd = (lane & 16) ? 16 : 0;
    #pragma unroll
    for (int t = 0; t < 2; t++) {
        uint32_t AH[2][4], AL[2][4], BW[2][4];
        #pragma unroll
        for (int mi = 0; mi < 2; mi++) {
            uint32_t off = swzA(wm * 32 + mi * 16 + rA, t * 32 + cadd);
            ldsm4(AH[mi], sb + stg + GSA_H + off);
            ldsm4(AL[mi], sb + stg + GSA_L + off);
        }
        #pragma unroll
        for (int j2 = 0; j2 < 2; j2++) {
            uint32_t off = swz(t * 16 + rA, wn * 64 + j2 * 32 + cadd);
            ldsm4t(BW[j2], sb + stg + GSB + off);
        }
        #pragma unroll
        for (int mi = 0; mi < 2; mi++) {
            #pragma unroll
            for (int j2 = 0; j2 < 2; j2++) {
                mma16816h(c[mi][2 * j2],     AH[mi], BW[j2][0], BW[j2][1]);
                mma16816h(c[mi][2 * j2 + 1], AH[mi], BW[j2][2], BW[j2][3]);
                mma16816h(c[mi][2 * j2],     AL[mi], BW[j2][0], BW[j2][1]);
                mma16816h(c[mi][2 * j2 + 1], AL[mi], BW[j2][2], BW[j2][3]);
            }
        }
    }
}

// K1: QKV GEMM (tensor). grid (24, 64).
__global__ __launch_bounds__(256) void gemm_qkv_mma()
{
    __shared__ char smem[2 * GSTAGE];
    const uint32_t sb = (uint32_t)__cvta_generic_to_shared(smem);
    const int tid = threadIdx.x;
    const int wid = tid >> 5, lane = tid & 31;
    const int wm = wid >> 1, wn = wid & 1;
    const int m0 = blockIdx.y * 128;
    const int n0 = blockIdx.x * 64;

    float c[2][4][4] = {};

    gemm_stage(sb, 0,      g_xh, g_xl, g_wq, m0, n0, 0,  QKVCOLS_, tid);
    cp_commit();
    gemm_stage(sb, GSTAGE, g_xh, g_xl, g_wq, m0, n0, 32, QKVCOLS_, tid);
    cp_commit();

    for (int kt = 0; kt < GNKT; kt++) {
        if (kt < GNKT - 1) cp_wait1(); else cp_wait0();
        __syncthreads();
        gemm_compute(sb, (kt & 1) * GSTAGE, c, wm, wn, lane);
        __syncthreads();
        if (kt + 2 < GNKT) {
            gemm_stage(sb, (kt & 1) * GSTAGE, g_xh, g_xl, g_wq,
                       m0, n0, (kt + 2) * 32, QKVCOLS_, tid);
            cp_commit();
        }
    }

    const int part = n0 >> 9;
    const int h = (n0 & 511) >> 6;
    float* dst = (part == 0) ? g_q : (part == 1) ? g_k : g_v;
    #pragma unroll
    for (int mi = 0; mi < 2; mi++) {
        #pragma unroll
        for (int r8 = 0; r8 < 2; r8++) {
            const int mrow = m0 + wm * 32 + mi * 16 + r8 * 8 + (lane >> 2);
            const int b = mrow >> 12;
            const int n = mrow & (N_ - 1);
            const size_t base = ((size_t)(b * H_ + h) * N_ + n) * D_;
            #pragma unroll
            for (int nj = 0; nj < 4; nj++) {
                const int dd = wn * 32 + nj * 8 + (lane & 3) * 2;
                *(float2*)&dst[base + dd] =
                    make_float2(c[mi][nj][2 * r8], c[mi][nj][2 * r8 + 1]);
            }
        }
    }
}

// K4: output GEMM (tensor). grid (8, 64).
__global__ __launch_bounds__(256) void gemm_out_mma(
    const float* __restrict__ bias, float* __restrict__ out)
{
    __shared__ char smem[2 * GSTAGE];
    const uint32_t sb = (uint32_t)__cvta_generic_to_shared(smem);
    const int tid = threadIdx.x;
    const int wid = tid >> 5, lane = tid & 31;
    const int wm = wid >> 1, wn = wid & 1;
    const int m0 = blockIdx.y * 128;
    const int n0 = blockIdx.x * 64;

    float c[2][4][4] = {};

    gemm_stage(sb, 0,      g_ohh, g_ohl, g_wo, m0, n0, 0,  C_, tid);
    cp_commit();
    gemm_stage(sb, GSTAGE, g_ohh, g_ohl, g_wo, m0, n0, 32, C_, tid);
    cp_commit();

    for (int kt = 0; kt < GNKT; kt++) {
        if (kt < GNKT - 1) cp_wait1(); else cp_wait0();
        __syncthreads();
        gemm_compute(sb, (kt & 1) * GSTAGE, c, wm, wn, lane);
        __syncthreads();
        if (kt + 2 < GNKT) {
            gemm_stage(sb, (kt & 1) * GSTAGE, g_ohh, g_ohl, g_wo,
                       m0, n0, (kt + 2) * 32, C_, tid);
            cp_commit();
        }
    }

    #pragma unroll
    for (int mi = 0; mi < 2; mi++) {
        #pragma unroll
        for (int r8 = 0; r8 < 2; r8++) {
            const int mrow = m0 + wm * 32 + mi * 16 + r8 * 8 + (lane >> 2);
            #pragma unroll
            for (int nj = 0; nj < 4; nj++) {
                const int col = n0 + wn * 32 + nj * 8 + (lane & 3) * 2;
                *(float2*)&out[(size_t)mrow * C_ + col] =
                    make_float2(c[mi][nj][2 * r8] + bias[col],
                                c[mi][nj][2 * r8 + 1] + bias[col + 1]);
            }
        }
    }
}

// ---------------------------------------------------------------------------
// K2: prep — RoPE(q,k) + scale q + fp16 conversion.
// ---------------------------------------------------------------------------
__global__ __launch_bounds__(256) void prep_kernel(const float* __restrict__ pos)
{
    const int tid = threadIdx.x;
    const int row = blockIdx.x * 4 + (tid >> 6);
    const int dd = tid & 63;
    const int n = row & (N_ - 1);
    const size_t idx = (size_t)row * D_ + dd;

    float sn, cs;
    __sincosf(pos[n * D_ + dd], &sn, &cs);
    const int partner = dd ^ 32;
    const float sign = (dd < 32) ? -1.0f : 1.0f;

    {
        const float t = g_q[idx];
        const float tp = g_q[(size_t)row * D_ + partner];
        g_qh[idx] = __float2half_rn((t * cs + sign * tp * sn) * SCALE_LOG2E);
    }
    {
        const float t = g_k[idx];
        const float tp = g_k[(size_t)row * D_ + partner];
        g_kh[idx] = __float2half_rn(t * cs + sign * tp * sn);
    }
    g_vh[idx] = __float2half_rn(g_v[idx]);
}

// ---------------------------------------------------------------------------
// K3: flash attention, pure fp16 mma.sync, BC=64, cp.async double-buffered.
// ---------------------------------------------------------------------------
#define BR 128
#define BC 64
#define NT (N_ / BC)       // 64

#define SQ    0
#define SKV   16384        // + stage*16384 ; K at +0, V at +8192
#define SMEM_BYTES 49152

__global__ __launch_bounds__(256, 2) void flash_mma_kernel()
{
    extern __shared__ char smraw[];
    const uint32_t sb = (uint32_t)__cvta_generic_to_shared(smraw);

    const int tid = threadIdx.x;
    const int wid = tid >> 5;
    const int lane = tid & 31;
    const int bh = blockIdx.y;
    const int b = bh >> 3, h = bh & 7;
    const int q0 = blockIdx.x * BR;

    // ---- stage Q ----
    {
        const size_t qbase = ((size_t)bh * N_ + q0) * D_;
        #pragma unroll
        for (int i = 0; i < 4; i++) {
            int c = tid + i * 256;            // 0..1023
            int row = c >> 3;
            int col16 = c & 7;
            cp16(sb + SQ + swz(row, col16 * 16),
                 g_qh + qbase + (size_t)row * D_ + col16 * 8);
        }
    }
    // ---- stage KV tile 0 (64 rows K + 64 rows V) ----
    {
        const size_t kvbase = (size_t)bh * N_ * D_;
        #pragma unroll
        for (int i = 0; i < 4; i++) {
            int c = tid + i * 256;            // 0..1023
            int arr = c >> 9;                 // 0=K, 1=V
            int cc = c & 511;
            int row = cc >> 3;                // 0..63
            int col16 = cc & 7;
            cp16(sb + SKV + (arr ? 8192 : 0) + swz(row, col16 * 16),
                 (arr ? g_vh : g_kh) + kvbase + (size_t)row * D_ + col16 * 8);
        }
    }
    cp_commit();
    cp_wait0();
    __syncthreads();

    // ---- Q fragments (registers, whole kernel) ----
    const int m0 = wid * 16;
    uint32_t qh[4][4];
    {
        int r = m0 + (lane & 15);
        int cadd = (lane & 16) ? 16 : 0;
        #pragma unroll
        for (int t = 0; t < 4; t++)
            ldsm4(qh[t], sb + SQ + swz(r, t * 32 + cadd));
    }

    float o[8][4] = {};
    float mrow0 = -1e30f, mrow1 = -1e30f;
    float lrow0 = 0.f, lrow1 = 0.f;

    const size_t kvstride = (size_t)bh * N_ * D_;

    for (int kt = 0; kt < NT; kt++) {
        const uint32_t buf = (kt & 1) ? 16384 : 0;
        const uint32_t nbuf = (kt & 1) ? 0 : 16384;

        if (kt + 1 < NT) {
            const size_t kvbase = kvstride + (size_t)(kt + 1) * BC * D_;
            #pragma unroll
            for (int i = 0; i < 4; i++) {
                int c = tid + i * 256;
                int arr = c >> 9;
                int cc = c & 511;
                int row = cc >> 3;
                int col16 = cc & 7;
                cp16(sb + SKV + nbuf + (arr ? 8192 : 0) + swz(row, col16 * 16),
                     (arr ? g_vh : g_kh) + kvbase + (size_t)row * D_ + col16 * 8);
            }
            cp_commit();
        }

        // ---- S = Q K^T  (8 n-blocks of 8 keys) ----
        float s[8][4] = {};
        {
            const int rbase = lane & 15;
            const int cadd = (lane & 16) ? 16 : 0;
            #pragma unroll
            for (int p = 0; p < 4; p++) {
                #pragma unroll
                for (int t = 0; t < 4; t++) {
                    uint32_t KH[4];
                    ldsm4(KH, sb + SKV + buf + swz(p * 16 + rbase, t * 32 + cadd));
                    mma16816h(s[2 * p],     qh[t], KH[0], KH[2]);
                    mma16816h(s[2 * p + 1], qh[t], KH[1], KH[3]);
                }
            }
        }

        // ---- online softmax (base-2, approx EX2) ----
        float rmax0 = -1e30f, rmax1 = -1e30f;
        #pragma unroll
        for (int ni = 0; ni < 8; ni++) {
            rmax0 = fmaxf(rmax0, fmaxf(s[ni][0], s[ni][1]));
            rmax1 = fmaxf(rmax1, fmaxf(s[ni][2], s[ni][3]));
        }
        rmax0 = fmaxf(rmax0, __shfl_xor_sync(0xffffffffu, rmax0, 1));
        rmax0 = fmaxf(rmax0, __shfl_xor_sync(0xffffffffu, rmax0, 2));
        rmax1 = fmaxf(rmax1, __shfl_xor_sync(0xffffffffu, rmax1, 1));
        rmax1 = fmaxf(rmax1, __shfl_xor_sync(0xffffffffu, rmax1, 2));

        const float mn0 = fmaxf(mrow0, rmax0);
        const float mn1 = fmaxf(mrow1, rmax1);
        const float a0 = ex2(mrow0 - mn0);
        const float a1 = ex2(mrow1 - mn1);
        mrow0 = mn0; mrow1 = mn1;

        float sum0 = 0.f, sum1 = 0.f;
        #pragma unroll
        for (int ni = 0; ni < 8; ni++) {
            s[ni][0] = ex2(s[ni][0] - mn0);
            s[ni][1] = ex2(s[ni][1] - mn0);
            s[ni][2] = ex2(s[ni][2] - mn1);
            s[ni][3] = ex2(s[ni][3] - mn1);
            sum0 += s[ni][0] + s[ni][1];
            sum1 += s[ni][2] + s[ni][3];
        }
        sum0 += __shfl_xor_sync(0xffffffffu, sum0, 1);
        sum0 += __shfl_xor_sync(0xffffffffu, sum0, 2);
        sum1 += __shfl_xor_sync(0xffffffffu, sum1, 1);
        sum1 += __shfl_xor_sync(0xffffffffu, sum1, 2);
        lrow0 = lrow0 * a0 + sum0;
        lrow1 = lrow1 * a1 + sum1;

        #pragma unroll
        for (int ni = 0; ni < 8; ni++) {
            o[ni][0] *= a0; o[ni][1] *= a0;
            o[ni][2] *= a1; o[ni][3] *= a1;
        }

        // ---- O += P V  (4 key-slabs of 16) ----
        #pragma unroll
        for (int t = 0; t < 4; t++) {
            uint32_t ah[4];
            {
                const float* p0 = s[2 * t];
                const float* p1 = s[2 * t + 1];
                ah[0] = u32h2(__floats2half2_rn(p0[0], p0[1]));
                ah[1] = u32h2(__floats2half2_rn(p0[2], p0[3]));
                ah[2] = u32h2(__floats2half2_rn(p1[0], p1[1]));
                ah[3] = u32h2(__floats2half2_rn(p1[2], p1[3]));
            }
            const int rr = t * 16 + (lane & 15);
            const int cadd = (lane & 16) ? 16 : 0;
            #pragma unroll
            for (int dp = 0; dp < 4; dp++) {
                uint32_t VH[4];
                ldsm4t(VH, sb + SKV + buf + 8192 + swz(rr, dp * 32 + cadd));
                mma16816h(o[2 * dp],     ah, VH[0], VH[1]);
                mma16816h(o[2 * dp + 1], ah, VH[2], VH[3]);
            }
        }

        cp_wait0();
        __syncthreads();
    }

    // ---- normalize + write O as fp16 hi/lo to [B,N,H*d] ----
    {
        const float inv0 = 1.0f / lrow0;
        const float inv1 = 1.0f / lrow1;
        const int r0 = q0 + m0 + (lane >> 2);
        const int cb = 2 * (lane & 3);
        const size_t base0 = ((size_t)(b * N_ + r0)) * INNER_ + h * D_;
        const size_t base1 = ((size_t)(b * N_ + r0 + 8)) * INNER_ + h * D_;
        #pragma unroll
        for (int ni = 0; ni < 8; ni++) {
            int dd = ni * 8 + cb;
            {
                float v0 = o[ni][0] * inv0, v1 = o[ni][1] * inv0;
                __half2 hv = __floats2half2_rn(v0, v1);
                float2 hf = __half22float2(hv);
                __half2 lv = __floats2half2_rn(v0 - hf.x, v1 - hf.y);
                *(uint32_t*)&g_ohh[base0 + dd] = u32h2(hv);
                *(uint32_t*)&g_ohl[base0 + dd] = u32h2(lv);
            }
            {
                float v0 = o[ni][2] * inv1, v1 = o[ni][3] * inv1;
                __half2 hv = __floats2half2_rn(v0, v1);
                float2 hf = __half22float2(hv);
                __half2 lv = __floats2half2_rn(v0 - hf.x, v1 - hf.y);
                *(uint32_t*)&g_ohh[base1 + dd] = u32h2(hv);
                *(uint32_t*)&g_ohl[base1 + dd] = u32h2(lv);
            }
        }
    }
}

// ---------------------------------------------------------------------------
extern "C" void kernel_launch(void* const* d_in, const int* in_sizes, int n_in,
                              void* d_out, int out_size)
{
    const float* x     = (const float*)d_in[0];
    const float* pos   = (const float*)d_in[1];
    const float* w_qkv = (const float*)d_in[2];
    const float* w_out = (const float*)d_in[3];
    const float* b_out = (const float*)d_in[4];
    float* out = (float*)d_out;

    static bool attr_set = false;
    if (!attr_set) {
        cudaFuncSetAttribute(flash_mma_kernel,
                             cudaFuncAttributeMaxDynamicSharedMemorySize,
                             SMEM_BYTES);
        attr_set = true;
    }

    void *p_xh, *p_xl, *p_wq, *p_wo;
    cudaGetSymbolAddress(&p_xh, g_xh);
    cudaGetSymbolAddress(&p_xl, g_xl);
    cudaGetSymbolAddress(&p_wq, g_wq);
    cudaGetSymbolAddress(&p_wo, g_wo);

    conv_split_h<<<(M_ * C_ / 4 + 255) / 256, 256>>>(
        (const float4*)x, (uint2*)p_xh, (uint2*)p_xl, M_ * C_ / 4);
    conv_single_h<<<(C_ * QKVCOLS_ / 4 + 255) / 256, 256>>>(
        (const float4*)w_qkv, (uint2*)p_wq, C_ * QKVCOLS_ / 4);
    conv_single_h<<<(INNER_ * C_ / 4 + 255) / 256, 256>>>(
        (const float4*)w_out, (uint2*)p_wo, INNER_ * C_ / 4);

    gemm_qkv_mma<<<dim3(QKVCOLS_ / 64, M_ / 128), 256>>>();

    prep_kernel<<<R_TOTAL / 4, 256>>>(pos);

    flash_mma_kernel<<<dim3(N_ / BR, B_ * H_), 256, SMEM_BYTES>>>();

    gemm_out_mma<<<dim3(C_ / 64, M_ / 128), 256>>>(b_out, out);
}

// round 9
// speedup vs baseline: 8.7094x; 1.0415x over previous
#include <cuda_runtime.h>
#include <cuda_bf16.h>
#include <cuda_fp16.h>
#include <cstdint>

// Problem constants
#define B_   2
#define N_   4096
#define C_   512
#define H_   8
#define D_   64
#define INNER_ (H_ * D_)          // 512
#define QKVCOLS_ (INNER_ * 3)     // 1536
#define M_ (B_ * N_)              // 8192
#define R_TOTAL (B_ * H_ * N_)    // 65536 rows of 64

// Scratch (device globals; no cudaMalloc allowed)
// fp16 attention inputs (post-RoPE, q pre-scaled) — written by qkv epilogue
__device__ __half g_qh[R_TOTAL * D_];
__device__ __half g_kh[R_TOTAL * D_];
__device__ __half g_vh[R_TOTAL * D_];
// fp16 GEMM inputs: activations hi/lo, weights single
__device__ __half g_xh[M_ * C_], g_xl[M_ * C_];
__device__ __half g_wq[C_ * QKVCOLS_];
__device__ __half g_wo[INNER_ * C_];
// attention output, fp16 hi/lo, [B,N,H*d]
__device__ __half g_ohh[B_ * N_ * INNER_], g_ohl[B_ * N_ * INNER_];

#define SCALE_LOG2E (0.125f * 1.4426950408889634f)

// ---------------------------------------------------------------------------
// common helpers
// ---------------------------------------------------------------------------
__device__ __forceinline__ uint32_t u32h2(__half2 v)
{
    return reinterpret_cast<uint32_t&>(v);
}
__device__ __forceinline__ float ex2(float x)
{
    float y;
    asm("ex2.approx.ftz.f32 %0, %1;" : "=f"(y) : "f"(x));
    return y;
}
__device__ __forceinline__ uint32_t swz(uint32_t row, uint32_t colb)
{
    uint32_t b = (row << 7) + colb;     // 128B rows
    return b ^ ((b >> 3) & 0x70);
}
__device__ __forceinline__ uint32_t swzA(uint32_t row, uint32_t colb)
{
    uint32_t b = (row << 6) + colb;     // 64B rows
    return b ^ ((b >> 3) & 0x30);
}
__device__ __forceinline__ void cp16(uint32_t dst, const void* src)
{
    asm volatile("cp.async.cg.shared.global [%0], [%1], 16;"
                 :: "r"(dst), "l"(src));
}
__device__ __forceinline__ void cp_commit()
{
    asm volatile("cp.async.commit_group;");
}
__device__ __forceinline__ void cp_wait0()
{
    asm volatile("cp.async.wait_group 0;");
}
__device__ __forceinline__ void cp_wait1()
{
    asm volatile("cp.async.wait_group 1;");
}
__device__ __forceinline__ void ldsm4(uint32_t a[4], uint32_t addr)
{
    asm volatile("ldmatrix.sync.aligned.m8n8.x4.shared.b16 {%0,%1,%2,%3}, [%4];"
                 : "=r"(a[0]), "=r"(a[1]), "=r"(a[2]), "=r"(a[3]) : "r"(addr));
}
__device__ __forceinline__ void ldsm4t(uint32_t a[4], uint32_t addr)
{
    asm volatile("ldmatrix.sync.aligned.m8n8.x4.trans.shared.b16 {%0,%1,%2,%3}, [%4];"
                 : "=r"(a[0]), "=r"(a[1]), "=r"(a[2]), "=r"(a[3]) : "r"(addr));
}
__device__ __forceinline__ void mma16816h(float c[4], const uint32_t a[4],
                                          uint32_t b0, uint32_t b1)
{
    asm volatile(
        "mma.sync.aligned.m16n8k16.row.col.f32.f16.f16.f32 "
        "{%0,%1,%2,%3}, {%4,%5,%6,%7}, {%8,%9}, {%0,%1,%2,%3};"
        : "+f"(c[0]), "+f"(c[1]), "+f"(c[2]), "+f"(c[3])
        : "r"(a[0]), "r"(a[1]), "r"(a[2]), "r"(a[3]), "r"(b0), "r"(b1));
}

// ---------------------------------------------------------------------------
// K0a: fp32 -> fp16 hi/lo split (activations)
// ---------------------------------------------------------------------------
__global__ __launch_bounds__(256) void conv_split_h(
    const float4* __restrict__ src, uint2* __restrict__ hi,
    uint2* __restrict__ lo, int n4)
{
    int i = blockIdx.x * 256 + threadIdx.x;
    if (i >= n4) return;
    float4 f = src[i];
    __half2 h0 = __floats2half2_rn(f.x, f.y);
    __half2 h1 = __floats2half2_rn(f.z, f.w);
    float2 a = __half22float2(h0), b = __half22float2(h1);
    __half2 l0 = __floats2half2_rn(f.x - a.x, f.y - a.y);
    __half2 l1 = __floats2half2_rn(f.z - b.x, f.w - b.y);
    hi[i] = make_uint2(u32h2(h0), u32h2(h1));
    lo[i] = make_uint2(u32h2(l0), u32h2(l1));
}

// K0b: fp32 -> fp16 single (weights)
__global__ __launch_bounds__(256) void conv_single_h(
    const float4* __restrict__ src, uint2* __restrict__ dst, int n4)
{
    int i = blockIdx.x * 256 + threadIdx.x;
    if (i >= n4) return;
    float4 f = src[i];
    dst[i] = make_uint2(u32h2(__floats2half2_rn(f.x, f.y)),
                        u32h2(__floats2half2_rn(f.z, f.w)));
}

// ---------------------------------------------------------------------------
// K1: QKV GEMM. BM=128, BN=128, BK=32, 2-stage cp.async, fp16 2-term.
// Warp tile 32x64 (8 warps: 4m x 2n). Epilogue fuses RoPE + fp16 convert.
// B smem: two 64-col SW128 sub-tiles (warp wn owns sub-tile wn).
// ---------------------------------------------------------------------------
#define QSA_H 0
#define QSA_L 8192
#define QSB   16384       // + half*4096
#define QSTAGE 24576
#define GNKT (C_ / 32)    // 16

__device__ __forceinline__ void qkv_stage(
    uint32_t sb, uint32_t stg, int m0, int n0, int k0, int tid)
{
    #pragma unroll
    for (int i = 0; i < 6; i++) {
        int c = tid + i * 256;               // 0..1535
        if (c < 512) {
            int row = c >> 2, col16 = c & 3;
            cp16(sb + stg + QSA_H + swzA(row, col16 * 16),
                 g_xh + (size_t)(m0 + row) * C_ + k0 + col16 * 8);
        } else if (c < 1024) {
            int cc = c - 512;
            int row = cc >> 2, col16 = cc & 3;
            cp16(sb + stg + QSA_L + swzA(row, col16 * 16),
                 g_xl + (size_t)(m0 + row) * C_ + k0 + col16 * 8);
        } else {
            int cc = c - 1024;               // 0..511
            int row = cc >> 4;               // 0..31
            int col16 = cc & 15;             // 0..15 (16B chunks across 128 cols)
            int half = col16 >> 3;
            cp16(sb + stg + QSB + half * 4096 + swz(row, (col16 & 7) * 16),
                 g_wq + (size_t)(k0 + row) * QKVCOLS_ + n0 + col16 * 8);
        }
    }
}

__global__ __launch_bounds__(256) void gemm_qkv_mma(const float* __restrict__ pos)
{
    __shared__ char smem[2 * QSTAGE];        // 48 KB
    const uint32_t sb = (uint32_t)__cvta_generic_to_shared(smem);
    const int tid = threadIdx.x;
    const int wid = tid >> 5, lane = tid & 31;
    const int wm = wid >> 1, wn = wid & 1;
    const int m0 = blockIdx.y * 128;
    const int n0 = blockIdx.x * 128;

    float c[2][8][4] = {};

    qkv_stage(sb, 0,      m0, n0, 0,  tid);
    cp_commit();
    qkv_stage(sb, QSTAGE, m0, n0, 32, tid);
    cp_commit();

    const int rA = lane & 15;
    const int cadd = (lane & 16) ? 16 : 0;

    for (int kt = 0; kt < GNKT; kt++) {
        if (kt < GNKT - 1) cp_wait1(); else cp_wait0();
        __syncthreads();
        const uint32_t stg = (kt & 1) * QSTAGE;
        #pragma unroll
        for (int t = 0; t < 2; t++) {
            uint32_t AH[2][4], AL[2][4], BW[4][4];
            #pragma unroll
            for (int mi = 0; mi < 2; mi++) {
                uint32_t off = swzA(wm * 32 + mi * 16 + rA, t * 32 + cadd);
                ldsm4(AH[mi], sb + stg + QSA_H + off);
                ldsm4(AL[mi], sb + stg + QSA_L + off);
            }
            #pragma unroll
            for (int j2 = 0; j2 < 4; j2++) {
                uint32_t off = swz(t * 16 + rA, j2 * 32 + cadd);
                ldsm4t(BW[j2], sb + stg + QSB + wn * 4096 + off);
            }
            #pragma unroll
            for (int mi = 0; mi < 2; mi++) {
                #pragma unroll
                for (int j2 = 0; j2 < 4; j2++) {
                    mma16816h(c[mi][2 * j2],     AH[mi], BW[j2][0], BW[j2][1]);
                    mma16816h(c[mi][2 * j2 + 1], AH[mi], BW[j2][2], BW[j2][3]);
                    mma16816h(c[mi][2 * j2],     AL[mi], BW[j2][0], BW[j2][1]);
                    mma16816h(c[mi][2 * j2 + 1], AL[mi], BW[j2][2], BW[j2][3]);
                }
            }
        }
        __syncthreads();
        if (kt + 2 < GNKT) {
            qkv_stage(sb, (kt & 1) * QSTAGE, m0, n0, (kt + 2) * 32, tid);
            cp_commit();
        }
    }

    // ---- fused epilogue: RoPE (q,k) + scale(q) + fp16 convert + scatter ----
    // Warp covers one full head's d-range: partner dd^32 == accumulator nj^4.
    const int part = n0 >> 9;                          // 0=q, 1=k, 2=v
    const int h = ((n0 + wn * 64) & 511) >> 6;
    __half* dst = (part == 0) ? g_qh : (part == 1) ? g_kh : g_vh;

    #pragma unroll
    for (int mi = 0; mi < 2; mi++) {
        #pragma unroll
        for (int r8 = 0; r8 < 2; r8++) {
            const int mrow = m0 + wm * 32 + mi * 16 + r8 * 8 + (lane >> 2);
            const int b = mrow >> 12;
            const int n = mrow & (N_ - 1);
            const size_t base = ((size_t)(b * H_ + h) * N_ + n) * D_;
            #pragma unroll
            for (int nj = 0; nj < 8; nj++) {
                const int dd = nj * 8 + (lane & 3) * 2;
                float v0 = c[mi][nj][2 * r8];
                float v1 = c[mi][nj][2 * r8 + 1];
                float r0, r1;
                if (part < 2) {
                    float s0, c0, s1, c1;
                    __sincosf(pos[n * D_ + dd],     &s0, &c0);
                    __sincosf(pos[n * D_ + dd + 1], &s1, &c1);
                    const float q0 = c[mi][nj ^ 4][2 * r8];
                    const float q1 = c[mi][nj ^ 4][2 * r8 + 1];
                    const float sign = (nj < 4) ? -1.0f : 1.0f;
                    r0 = v0 * c0 + sign * q0 * s0;
                    r1 = v1 * c1 + sign * q1 * s1;
                    if (part == 0) { r0 *= SCALE_LOG2E; r1 *= SCALE_LOG2E; }
                } else {
                    r0 = v0; r1 = v1;
                }
                *(uint32_t*)&dst[base + dd] = u32h2(__floats2half2_rn(r0, r1));
            }
        }
    }
}

// ---------------------------------------------------------------------------
// K4: output GEMM. BM=128, BN=64, BK=32, fp16 2-term (unchanged).
// ---------------------------------------------------------------------------
#define GSA_H 0
#define GSA_L 8192
#define GSB   16384
#define GSTAGE 20480

__device__ __forceinline__ void out_stage(
    uint32_t sb, uint32_t stg, int m0, int n0, int k0, int tid)
{
    #pragma unroll
    for (int i = 0; i < 5; i++) {
        int c = tid + i * 256;               // 0..1279
        if (c < 512) {
            int row = c >> 2, col16 = c & 3;
            cp16(sb + stg + GSA_H + swzA(row, col16 * 16),
                 g_ohh + (size_t)(m0 + row) * C_ + k0 + col16 * 8);
        } else if (c < 1024) {
            int cc = c - 512;
            int row = cc >> 2, col16 = cc & 3;
            cp16(sb + stg + GSA_L + swzA(row, col16 * 16),
                 g_ohl + (size_t)(m0 + row) * C_ + k0 + col16 * 8);
        } else {
            int cc = c - 1024;
            int row = cc >> 3, col16 = cc & 7;
            cp16(sb + stg + GSB + swz(row, col16 * 16),
                 g_wo + (size_t)(k0 + row) * C_ + n0 + col16 * 8);
        }
    }
}

__global__ __launch_bounds__(256) void gemm_out_mma(
    const float* __restrict__ bias, float* __restrict__ out)
{
    __shared__ char smem[2 * GSTAGE];
    const uint32_t sb = (uint32_t)__cvta_generic_to_shared(smem);
    const int tid = threadIdx.x;
    const int wid = tid >> 5, lane = tid & 31;
    const int wm = wid >> 1, wn = wid & 1;
    const int m0 = blockIdx.y * 128;
    const int n0 = blockIdx.x * 64;

    float c[2][4][4] = {};

    out_stage(sb, 0,      m0, n0, 0,  tid);
    cp_commit();
    out_stage(sb, GSTAGE, m0, n0, 32, tid);
    cp_commit();

    const int rA = lane & 15;
    const int cadd = (lane & 16) ? 16 : 0;

    for (int kt = 0; kt < GNKT; kt++) {
        if (kt < GNKT - 1) cp_wait1(); else cp_wait0();
        __syncthreads();
        const uint32_t stg = (kt & 1) * GSTAGE;
        #pragma unroll
        for (int t = 0; t < 2; t++) {
            uint32_t AH[2][4], AL[2][4], BW[2][4];
            #pragma unroll
            for (int mi = 0; mi < 2; mi++) {
                uint32_t off = swzA(wm * 32 + mi * 16 + rA, t * 32 + cadd);
                ldsm4(AH[mi], sb + stg + GSA_H + off);
                ldsm4(AL[mi], sb + stg + GSA_L + off);
            }
            #pragma unroll
            for (int j2 = 0; j2 < 2; j2++) {
                uint32_t off = swz(t * 16 + rA, wn * 64 + j2 * 32 + cadd);
                ldsm4t(BW[j2], sb + stg + GSB + off);
            }
            #pragma unroll
            for (int mi = 0; mi < 2; mi++) {
                #pragma unroll
                for (int j2 = 0; j2 < 2; j2++) {
                    mma16816h(c[mi][2 * j2],     AH[mi], BW[j2][0], BW[j2][1]);
                    mma16816h(c[mi][2 * j2 + 1], AH[mi], BW[j2][2], BW[j2][3]);
                    mma16816h(c[mi][2 * j2],     AL[mi], BW[j2][0], BW[j2][1]);
                    mma16816h(c[mi][2 * j2 + 1], AL[mi], BW[j2][2], BW[j2][3]);
                }
            }
        }
        __syncthreads();
        if (kt + 2 < GNKT) {
            out_stage(sb, (kt & 1) * GSTAGE, m0, n0, (kt + 2) * 32, tid);
            cp_commit();
        }
    }

    #pragma unroll
    for (int mi = 0; mi < 2; mi++) {
        #pragma unroll
        for (int r8 = 0; r8 < 2; r8++) {
            const int mrow = m0 + wm * 32 + mi * 16 + r8 * 8 + (lane >> 2);
            #pragma unroll
            for (int nj = 0; nj < 4; nj++) {
                const int col = n0 + wn * 32 + nj * 8 + (lane & 3) * 2;
                *(float2*)&out[(size_t)mrow * C_ + col] =
                    make_float2(c[mi][nj][2 * r8] + bias[col],
                                c[mi][nj][2 * r8 + 1] + bias[col + 1]);
            }
        }
    }
}

// ---------------------------------------------------------------------------
// K3: flash attention, pure fp16 mma.sync, BC=64, cp.async double-buffered.
// ---------------------------------------------------------------------------
#define BR 128
#define BC 64
#define NT (N_ / BC)       // 64

#define SQ    0
#define SKV   16384        // + stage*16384 ; K at +0, V at +8192
#define SMEM_BYTES 49152

__global__ __launch_bounds__(256, 2) void flash_mma_kernel()
{
    extern __shared__ char smraw[];
    const uint32_t sb = (uint32_t)__cvta_generic_to_shared(smraw);

    const int tid = threadIdx.x;
    const int wid = tid >> 5;
    const int lane = tid & 31;
    const int bh = blockIdx.y;
    const int b = bh >> 3, h = bh & 7;
    const int q0 = blockIdx.x * BR;

    // ---- stage Q ----
    {
        const size_t qbase = ((size_t)bh * N_ + q0) * D_;
        #pragma unroll
        for (int i = 0; i < 4; i++) {
            int c = tid + i * 256;            // 0..1023
            int row = c >> 3;
            int col16 = c & 7;
            cp16(sb + SQ + swz(row, col16 * 16),
                 g_qh + qbase + (size_t)row * D_ + col16 * 8);
        }
    }
    // ---- stage KV tile 0 ----
    {
        const size_t kvbase = (size_t)bh * N_ * D_;
        #pragma unroll
        for (int i = 0; i < 4; i++) {
            int c = tid + i * 256;            // 0..1023
            int arr = c >> 9;                 // 0=K, 1=V
            int cc = c & 511;
            int row = cc >> 3;                // 0..63
            int col16 = cc & 7;
            cp16(sb + SKV + (arr ? 8192 : 0) + swz(row, col16 * 16),
                 (arr ? g_vh : g_kh) + kvbase + (size_t)row * D_ + col16 * 8);
        }
    }
    cp_commit();
    cp_wait0();
    __syncthreads();

    // ---- Q fragments (registers, whole kernel) ----
    const int m0 = wid * 16;
    uint32_t qh[4][4];
    {
        int r = m0 + (lane & 15);
        int cadd = (lane & 16) ? 16 : 0;
        #pragma unroll
        for (int t = 0; t < 4; t++)
            ldsm4(qh[t], sb + SQ + swz(r, t * 32 + cadd));
    }

    float o[8][4] = {};
    float mrow0 = -1e30f, mrow1 = -1e30f;
    float lrow0 = 0.f, lrow1 = 0.f;

    const size_t kvstride = (size_t)bh * N_ * D_;

    for (int kt = 0; kt < NT; kt++) {
        const uint32_t buf = (kt & 1) ? 16384 : 0;
        const uint32_t nbuf = (kt & 1) ? 0 : 16384;

        if (kt + 1 < NT) {
            const size_t kvbase = kvstride + (size_t)(kt + 1) * BC * D_;
            #pragma unroll
            for (int i = 0; i < 4; i++) {
                int c = tid + i * 256;
                int arr = c >> 9;
                int cc = c & 511;
                int row = cc >> 3;
                int col16 = cc & 7;
                cp16(sb + SKV + nbuf + (arr ? 8192 : 0) + swz(row, col16 * 16),
                     (arr ? g_vh : g_kh) + kvbase + (size_t)row * D_ + col16 * 8);
            }
            cp_commit();
        }

        // ---- S = Q K^T ----
        float s[8][4] = {};
        {
            const int rbase = lane & 15;
            const int cadd = (lane & 16) ? 16 : 0;
            #pragma unroll
            for (int p = 0; p < 4; p++) {
                #pragma unroll
                for (int t = 0; t < 4; t++) {
                    uint32_t KH[4];
                    ldsm4(KH, sb + SKV + buf + swz(p * 16 + rbase, t * 32 + cadd));
                    mma16816h(s[2 * p],     qh[t], KH[0], KH[2]);
                    mma16816h(s[2 * p + 1], qh[t], KH[1], KH[3]);
                }
            }
        }

        // ---- online softmax (base-2, approx EX2) ----
        float rmax0 = -1e30f, rmax1 = -1e30f;
        #pragma unroll
        for (int ni = 0; ni < 8; ni++) {
            rmax0 = fmaxf(rmax0, fmaxf(s[ni][0], s[ni][1]));
            rmax1 = fmaxf(rmax1, fmaxf(s[ni][2], s[ni][3]));
        }
        rmax0 = fmaxf(rmax0, __shfl_xor_sync(0xffffffffu, rmax0, 1));
        rmax0 = fmaxf(rmax0, __shfl_xor_sync(0xffffffffu, rmax0, 2));
        rmax1 = fmaxf(rmax1, __shfl_xor_sync(0xffffffffu, rmax1, 1));
        rmax1 = fmaxf(rmax1, __shfl_xor_sync(0xffffffffu, rmax1, 2));

        const float mn0 = fmaxf(mrow0, rmax0);
        const float mn1 = fmaxf(mrow1, rmax1);
        const float a0 = ex2(mrow0 - mn0);
        const float a1 = ex2(mrow1 - mn1);
        mrow0 = mn0; mrow1 = mn1;

        float sum0 = 0.f, sum1 = 0.f;
        #pragma unroll
        for (int ni = 0; ni < 8; ni++) {
            s[ni][0] = ex2(s[ni][0] - mn0);
            s[ni][1] = ex2(s[ni][1] - mn0);
            s[ni][2] = ex2(s[ni][2] - mn1);
            s[ni][3] = ex2(s[ni][3] - mn1);
            sum0 += s[ni][0] + s[ni][1];
            sum1 += s[ni][2] + s[ni][3];
        }
        sum0 += __shfl_xor_sync(0xffffffffu, sum0, 1);
        sum0 += __shfl_xor_sync(0xffffffffu, sum0, 2);
        sum1 += __shfl_xor_sync(0xffffffffu, sum1, 1);
        sum1 += __shfl_xor_sync(0xffffffffu, sum1, 2);
        lrow0 = lrow0 * a0 + sum0;
        lrow1 = lrow1 * a1 + sum1;

        #pragma unroll
        for (int ni = 0; ni < 8; ni++) {
            o[ni][0] *= a0; o[ni][1] *= a0;
            o[ni][2] *= a1; o[ni][3] *= a1;
        }

        // ---- O += P V ----
        #pragma unroll
        for (int t = 0; t < 4; t++) {
            uint32_t ah[4];
            {
                const float* p0 = s[2 * t];
                const float* p1 = s[2 * t + 1];
                ah[0] = u32h2(__floats2half2_rn(p0[0], p0[1]));
                ah[1] = u32h2(__floats2half2_rn(p0[2], p0[3]));
                ah[2] = u32h2(__floats2half2_rn(p1[0], p1[1]));
                ah[3] = u32h2(__floats2half2_rn(p1[2], p1[3]));
            }
            const int rr = t * 16 + (lane & 15);
            const int cadd = (lane & 16) ? 16 : 0;
            #pragma unroll
            for (int dp = 0; dp < 4; dp++) {
                uint32_t VH[4];
                ldsm4t(VH, sb + SKV + buf + 8192 + swz(rr, dp * 32 + cadd));
                mma16816h(o[2 * dp],     ah, VH[0], VH[1]);
                mma16816h(o[2 * dp + 1], ah, VH[2], VH[3]);
            }
        }

        cp_wait0();
        __syncthreads();
    }

    // ---- normalize + write O as fp16 hi/lo to [B,N,H*d] ----
    {
        const float inv0 = 1.0f / lrow0;
        const float inv1 = 1.0f / lrow1;
        const int r0 = q0 + m0 + (lane >> 2);
        const int cb = 2 * (lane & 3);
        const size_t base0 = ((size_t)(b * N_ + r0)) * INNER_ + h * D_;
        const size_t base1 = ((size_t)(b * N_ + r0 + 8)) * INNER_ + h * D_;
        #pragma unroll
        for (int ni = 0; ni < 8; ni++) {
            int dd = ni * 8 + cb;
            {
                float v0 = o[ni][0] * inv0, v1 = o[ni][1] * inv0;
                __half2 hv = __floats2half2_rn(v0, v1);
                float2 hf = __half22float2(hv);
                __half2 lv = __floats2half2_rn(v0 - hf.x, v1 - hf.y);
                *(uint32_t*)&g_ohh[base0 + dd] = u32h2(hv);
                *(uint32_t*)&g_ohl[base0 + dd] = u32h2(lv);
            }
            {
                float v0 = o[ni][2] * inv1, v1 = o[ni][3] * inv1;
                __half2 hv = __floats2half2_rn(v0, v1);
                float2 hf = __half22float2(hv);
                __half2 lv = __floats2half2_rn(v0 - hf.x, v1 - hf.y);
                *(uint32_t*)&g_ohh[base1 + dd] = u32h2(hv);
                *(uint32_t*)&g_ohl[base1 + dd] = u32h2(lv);
            }
        }
    }
}

// ---------------------------------------------------------------------------
extern "C" void kernel_launch(void* const* d_in, const int* in_sizes, int n_in,
                              void* d_out, int out_size)
{
    const float* x     = (const float*)d_in[0];
    const float* pos   = (const float*)d_in[1];
    const float* w_qkv = (const float*)d_in[2];
    const float* w_out = (const float*)d_in[3];
    const float* b_out = (const float*)d_in[4];
    float* out = (float*)d_out;

    static bool attr_set = false;
    if (!attr_set) {
        cudaFuncSetAttribute(flash_mma_kernel,
                             cudaFuncAttributeMaxDynamicSharedMemorySize,
                             SMEM_BYTES);
        attr_set = true;
    }

    void *p_xh, *p_xl, *p_wq, *p_wo;
    cudaGetSymbolAddress(&p_xh, g_xh);
    cudaGetSymbolAddress(&p_xl, g_xl);
    cudaGetSymbolAddress(&p_wq, g_wq);
    cudaGetSymbolAddress(&p_wo, g_wo);

    conv_split_h<<<(M_ * C_ / 4 + 255) / 256, 256>>>(
        (const float4*)x, (uint2*)p_xh, (uint2*)p_xl, M_ * C_ / 4);
    conv_single_h<<<(C_ * QKVCOLS_ / 4 + 255) / 256, 256>>>(
        (const float4*)w_qkv, (uint2*)p_wq, C_ * QKVCOLS_ / 4);
    conv_single_h<<<(INNER_ * C_ / 4 + 255) / 256, 256>>>(
        (const float4*)w_out, (uint2*)p_wo, INNER_ * C_ / 4);

    gemm_qkv_mma<<<dim3(QKVCOLS_ / 128, M_ / 128), 256>>>(pos);

    flash_mma_kernel<<<dim3(N_ / BR, B_ * H_), 256, SMEM_BYTES>>>();

    gemm_out_mma<<<dim3(C_ / 64, M_ / 128), 256>>>(b_out, out);
}